// round 1
// baseline (speedup 1.0000x reference)
#include <cuda_runtime.h>
#include <math.h>

#define NN 50000
#define NE 600000

// Scratch (allocation-free: static __device__ globals)
__device__ float g_X [NN * 128];   // [n][m(0..3)][c]  m=0 -> x0, m=1..3 -> x1
__device__ float g_M0[NN * 64];    // [n][s(0:p0,1:p3)][c]
__device__ float g_M1[NN * 288];   // [n][p(0:p1,1:p2,2:p4)][m(0..2)][c]

__device__ __forceinline__ float act(float x) {
    // RS * silu(x)
    return 1.6765324703310907f * x * (1.0f / (1.0f + __expf(-x)));
}

// ---------------------------------------------------------------------------
// K1: per-node skip connection (sc -> out) and first linear (x -> g_X)
// warp per node, lane = output channel w/d
// ---------------------------------------------------------------------------
__global__ void __launch_bounds__(128) k_node(
    const float* __restrict__ na,     // (N, 10)
    const float* __restrict__ nf,     // (N, 32, 4)
    const float* __restrict__ Wskip,  // (2, 32, 10, 32)
    const float* __restrict__ Wfirst, // (2, 32, 32)
    float* __restrict__ out_sc)       // out + NN*128
{
    extern __shared__ float s[];
    float* sW0  = s;          // 10240 : [c][v][w]
    float* sW1  = s + 10240;  // 10240 : [c][v][w]
    float* sWfT = s + 20480;  // 2048  : [skip][c][d]
    for (int t = threadIdx.x; t < 20480; t += blockDim.x) s[t] = Wskip[t];
    for (int t = threadIdx.x; t < 2048; t += blockDim.x) {
        int skip = t >> 10; int r = t & 1023; int d = r >> 5; int c = r & 31;
        sWfT[skip * 1024 + c * 32 + d] = Wfirst[t];
    }
    __syncthreads();

    int lane  = threadIdx.x & 31;
    int warp  = threadIdx.x >> 5;
    int nwarp = (blockDim.x >> 5) * gridDim.x;
    for (int n = blockIdx.x * (blockDim.x >> 5) + warp; n < NN; n += nwarp) {
        float nav[10];
        #pragma unroll
        for (int v = 0; v < 10; v++) nav[v] = na[n * 10 + v];

        float acc0 = 0.f, a10 = 0.f, a11 = 0.f, a12 = 0.f;
        float x0 = 0.f, x1 = 0.f, x2 = 0.f, x3 = 0.f;
        const float4* nf4 = (const float4*)(nf + (size_t)n * 128);
        #pragma unroll 4
        for (int c = 0; c < 32; c++) {
            float4 f = nf4[c];
            float A = 0.f, B = 0.f;
            #pragma unroll
            for (int v = 0; v < 10; v++) {
                A += nav[v] * sW0[(c * 10 + v) * 32 + lane];
                B += nav[v] * sW1[(c * 10 + v) * 32 + lane];
            }
            acc0 += f.x * A;
            a10  += f.y * B; a11 += f.z * B; a12 += f.w * B;
            float w0 = sWfT[c * 32 + lane];
            float w1 = sWfT[1024 + c * 32 + lane];
            x0 += f.x * w0; x1 += f.y * w1; x2 += f.z * w1; x3 += f.w * w1;
        }
        const float s320 = 0.05590169943749474f;   // 1/sqrt(320)
        const float sC   = 0.17677669529663687f;   // 1/sqrt(32)
        float4 scv = make_float4(acc0 * s320, a10 * s320, a11 * s320, a12 * s320);
        *(float4*)(out_sc + (size_t)n * 128 + lane * 4) = scv;
        float* xo = g_X + (size_t)n * 128;
        xo[lane]      = x0 * sC;
        xo[32 + lane] = x1 * sC;
        xo[64 + lane] = x2 * sC;
        xo[96 + lane] = x3 * sC;
    }
}

// ---------------------------------------------------------------------------
// K2: per-edge MLP + gather + segmented accumulation
// warp cooperates on one edge; each warp owns a contiguous chunk of (sorted) edges
// ---------------------------------------------------------------------------
__global__ void __launch_bounds__(256) k_edge(
    const float* __restrict__ ef,     // (E, 8)
    const float* __restrict__ ea,     // (E, 1, 4)
    const int*   __restrict__ idx_i,  // (E,) sorted
    const int*   __restrict__ idx_j,  // (E,)
    const float* __restrict__ Wr0,    // (64, 8)
    const float* __restrict__ Wr1,    // (64, 64)
    const float* __restrict__ Wr2,    // (64, 64)
    const float* __restrict__ Wr3)    // (160, 64)
{
    extern __shared__ float s[];
    float2* sW0  = (float2*)s;             // 256  [k][j]   (.x=j, .y=j+32)
    float2* sW1  = (float2*)(s + 512);     // 2048 [k][j]
    float2* sW2  = (float2*)(s + 4608);    // 2048 [k][j]
    float4* sW3a = (float4*)(s + 8704);    // 2048 [k][c] paths 0..3
    float*  sW3b = s + 16896;              // 2048 [k][c] path 4
    // total = 18944 floats = 75776 B

    for (int t = threadIdx.x; t < 256; t += blockDim.x) {
        int k = t >> 5, j = t & 31;
        sW0[t] = make_float2(Wr0[j * 8 + k], Wr0[(j + 32) * 8 + k]);
    }
    for (int t = threadIdx.x; t < 2048; t += blockDim.x) {
        int k = t >> 5, j = t & 31;
        sW1[t] = make_float2(Wr1[j * 64 + k], Wr1[(j + 32) * 64 + k]);
        sW2[t] = make_float2(Wr2[j * 64 + k], Wr2[(j + 32) * 64 + k]);
        int c = j;
        sW3a[t] = make_float4(Wr3[c * 64 + k], Wr3[(32 + c) * 64 + k],
                              Wr3[(64 + c) * 64 + k], Wr3[(96 + c) * 64 + k]);
        sW3b[t] = Wr3[(128 + c) * 64 + k];
    }
    __syncthreads();

    int lane = threadIdx.x & 31;
    int gw   = blockIdx.x * (blockDim.x >> 5) + (threadIdx.x >> 5);
    int nw   = gridDim.x * (blockDim.x >> 5);
    int per  = (NE + nw - 1) / nw;
    int e0   = gw * per;
    int e1   = (e0 + per < NE) ? (e0 + per) : NE;
    if (e0 >= e1) return;

    float a0 = 0.f, a3 = 0.f;
    float a1x = 0.f, a1y = 0.f, a1z = 0.f;
    float a2x = 0.f, a2y = 0.f, a2z = 0.f;
    float a4x = 0.f, a4y = 0.f, a4z = 0.f;
    int cur = idx_i[e0];

    for (int e = e0; e < e1; e++) {
        int ni = idx_i[e];
        if (ni != cur) {
            atomicAdd(&g_M0[(size_t)cur * 64 + lane],      a0);
            atomicAdd(&g_M0[(size_t)cur * 64 + 32 + lane], a3);
            float* m1 = g_M1 + (size_t)cur * 288 + lane;
            atomicAdd(m1 + 0,   a1x); atomicAdd(m1 + 32,  a1y); atomicAdd(m1 + 64,  a1z);
            atomicAdd(m1 + 96,  a2x); atomicAdd(m1 + 128, a2y); atomicAdd(m1 + 160, a2z);
            atomicAdd(m1 + 192, a4x); atomicAdd(m1 + 224, a4y); atomicAdd(m1 + 256, a4z);
            a0 = a3 = a1x = a1y = a1z = a2x = a2y = a2z = a4x = a4y = a4z = 0.f;
            cur = ni;
        }

        // ----- MLP: h distributed 2 values / lane (lo=h[lane], hi=h[lane+32])
        float efr = (lane < 8) ? ef[(size_t)e * 8 + lane] : 0.f;
        float lo = 0.f, hi = 0.f;
        #pragma unroll
        for (int k = 0; k < 8; k++) {
            float b = __shfl_sync(0xffffffffu, efr, k);
            float2 W = sW0[k * 32 + lane];
            lo += b * W.x; hi += b * W.y;
        }
        lo = act(lo * 0.35355339059327373f);
        hi = act(hi * 0.35355339059327373f);

        float nlo = 0.f, nhi = 0.f;
        #pragma unroll
        for (int k = 0; k < 32; k++) {
            float b = __shfl_sync(0xffffffffu, lo, k);
            float2 W = sW1[k * 32 + lane];
            nlo += b * W.x; nhi += b * W.y;
        }
        #pragma unroll
        for (int k = 0; k < 32; k++) {
            float b = __shfl_sync(0xffffffffu, hi, k);
            float2 W = sW1[(k + 32) * 32 + lane];
            nlo += b * W.x; nhi += b * W.y;
        }
        lo = act(nlo * 0.125f); hi = act(nhi * 0.125f);

        nlo = 0.f; nhi = 0.f;
        #pragma unroll
        for (int k = 0; k < 32; k++) {
            float b = __shfl_sync(0xffffffffu, lo, k);
            float2 W = sW2[k * 32 + lane];
            nlo += b * W.x; nhi += b * W.y;
        }
        #pragma unroll
        for (int k = 0; k < 32; k++) {
            float b = __shfl_sync(0xffffffffu, hi, k);
            float2 W = sW2[(k + 32) * 32 + lane];
            nlo += b * W.x; nhi += b * W.y;
        }
        lo = act(nlo * 0.125f); hi = act(nhi * 0.125f);

        float w0 = 0.f, w1 = 0.f, w2 = 0.f, w3 = 0.f, w4 = 0.f;
        #pragma unroll
        for (int k = 0; k < 32; k++) {
            float b = __shfl_sync(0xffffffffu, lo, k);
            float4 W = sW3a[k * 32 + lane];
            float  V = sW3b[k * 32 + lane];
            w0 += b * W.x; w1 += b * W.y; w2 += b * W.z; w3 += b * W.w; w4 += b * V;
        }
        #pragma unroll
        for (int k = 0; k < 32; k++) {
            float b = __shfl_sync(0xffffffffu, hi, k);
            float4 W = sW3a[(k + 32) * 32 + lane];
            float  V = sW3b[(k + 32) * 32 + lane];
            w0 += b * W.x; w1 += b * W.y; w2 += b * W.z; w3 += b * W.w; w4 += b * V;
        }
        w0 *= 0.125f; w1 *= 0.125f; w2 *= 0.125f; w3 *= 0.125f; w4 *= 0.125f;

        // ----- gather + path products (lane = channel c)
        int j = idx_j[e];
        const float* xb = g_X + (size_t)j * 128;
        float xj0 = xb[lane];
        float xa  = xb[32 + lane];
        float xbv = xb[64 + lane];
        float xc  = xb[96 + lane];
        float4 y = *(const float4*)(ea + (size_t)e * 4);  // y0, y1x, y1y, y1z

        a0 += w0 * xj0 * y.x;
        float t1 = w1 * xj0;
        a1x += t1 * y.y; a1y += t1 * y.z; a1z += t1 * y.w;
        a2x += w2 * xa * y.x; a2y += w2 * xbv * y.x; a2z += w2 * xc * y.x;
        a3  += w3 * (xa * y.y + xbv * y.z + xc * y.w);
        a4x += w4 * (xbv * y.w - xc * y.z);
        a4y += w4 * (xc * y.y - xa * y.w);
        a4z += w4 * (xa * y.z - xbv * y.y);
    }
    // final flush
    atomicAdd(&g_M0[(size_t)cur * 64 + lane],      a0);
    atomicAdd(&g_M0[(size_t)cur * 64 + 32 + lane], a3);
    float* m1 = g_M1 + (size_t)cur * 288 + lane;
    atomicAdd(m1 + 0,   a1x); atomicAdd(m1 + 32,  a1y); atomicAdd(m1 + 64,  a1z);
    atomicAdd(m1 + 96,  a2x); atomicAdd(m1 + 128, a2y); atomicAdd(m1 + 160, a2z);
    atomicAdd(m1 + 192, a4x); atomicAdd(m1 + 224, a4y); atomicAdd(m1 + 256, a4z);
}

// ---------------------------------------------------------------------------
// K3: per-node second linear -> message output. warp per node, lane = d
// ---------------------------------------------------------------------------
__global__ void __launch_bounds__(128) k_out(
    const float* __restrict__ Ws0,  // (32, 64)
    const float* __restrict__ Ws1,  // (32, 96)
    float* __restrict__ out)        // message at out[0 .. NN*128)
{
    __shared__ float sW0T[64 * 32];   // [t=p*32+c][d]
    __shared__ float sW1T[96 * 32];   // [t=p*32+c][d]
    for (int t = threadIdx.x; t < 2048; t += blockDim.x) {
        int d = t >> 6, k = t & 63;
        sW0T[k * 32 + d] = Ws0[t];
    }
    for (int t = threadIdx.x; t < 3072; t += blockDim.x) {
        int d = t / 96, k = t % 96;
        sW1T[k * 32 + d] = Ws1[t];
    }
    __syncthreads();

    int lane  = threadIdx.x & 31;
    int warp  = threadIdx.x >> 5;
    int nwarp = (blockDim.x >> 5) * gridDim.x;
    const float sA  = 1.0f / 12.0f;
    const float s64 = 0.125f;
    const float s96 = 0.10206207261596575f;

    for (int n = blockIdx.x * (blockDim.x >> 5) + warp; n < NN; n += nwarp) {
        const float4* m0 = (const float4*)(g_M0 + (size_t)n * 64);
        float o0 = 0.f;
        #pragma unroll
        for (int t = 0; t < 16; t++) {
            float4 v = m0[t];
            o0 += v.x * sW0T[(t * 4 + 0) * 32 + lane]
                + v.y * sW0T[(t * 4 + 1) * 32 + lane]
                + v.z * sW0T[(t * 4 + 2) * 32 + lane]
                + v.w * sW0T[(t * 4 + 3) * 32 + lane];
        }
        float o1x = 0.f, o1y = 0.f, o1z = 0.f;
        #pragma unroll
        for (int p = 0; p < 3; p++) {
            const float4* m1 = (const float4*)(g_M1 + (size_t)n * 288 + p * 96);
            #pragma unroll
            for (int q = 0; q < 8; q++) {
                float4 vx = m1[q];        // m=0
                float4 vy = m1[8 + q];    // m=1
                float4 vz = m1[16 + q];   // m=2
                float wA = sW1T[(p * 32 + q * 4 + 0) * 32 + lane];
                float wB = sW1T[(p * 32 + q * 4 + 1) * 32 + lane];
                float wC = sW1T[(p * 32 + q * 4 + 2) * 32 + lane];
                float wD = sW1T[(p * 32 + q * 4 + 3) * 32 + lane];
                o1x += vx.x * wA + vx.y * wB + vx.z * wC + vx.w * wD;
                o1y += vy.x * wA + vy.y * wB + vy.z * wC + vy.w * wD;
                o1z += vz.x * wA + vz.y * wB + vz.z * wC + vz.w * wD;
            }
        }
        float4 r = make_float4(o0 * s64 * sA, o1x * s96 * sA, o1y * s96 * sA, o1z * s96 * sA);
        *(float4*)(out + (size_t)n * 128 + lane * 4) = r;
    }
}

// ---------------------------------------------------------------------------
extern "C" void kernel_launch(void* const* d_in, const int* in_sizes, int n_in,
                              void* d_out, int out_size)
{
    const float* na     = (const float*)d_in[0];   // node_attrs
    const float* nf     = (const float*)d_in[1];   // node_feats
    const float* ea     = (const float*)d_in[2];   // edge_attrs
    const float* ef     = (const float*)d_in[3];   // edge_feats
    const float* Wfirst = (const float*)d_in[4];
    const float* Wr0    = (const float*)d_in[5];
    const float* Wr1    = (const float*)d_in[6];
    const float* Wr2    = (const float*)d_in[7];
    const float* Wr3    = (const float*)d_in[8];
    const float* Ws0    = (const float*)d_in[9];
    const float* Ws1    = (const float*)d_in[10];
    const float* Wskip  = (const float*)d_in[11];
    const int*   idx_i  = (const int*)d_in[12];
    const int*   idx_j  = (const int*)d_in[13];
    float* out = (float*)d_out;

    cudaFuncSetAttribute(k_node, cudaFuncAttributeMaxDynamicSharedMemorySize, 22528 * 4);
    cudaFuncSetAttribute(k_edge, cudaFuncAttributeMaxDynamicSharedMemorySize, 18944 * 4);

    void *pM0, *pM1;
    cudaGetSymbolAddress(&pM0, g_M0);
    cudaGetSymbolAddress(&pM1, g_M1);
    cudaMemsetAsync(pM0, 0, sizeof(float) * NN * 64, 0);
    cudaMemsetAsync(pM1, 0, sizeof(float) * NN * 288, 0);

    // K1: sc -> out[NN*128 ..), x -> g_X
    k_node<<<296, 128, 22528 * 4>>>(na, nf, Wskip, Wfirst, out + (size_t)NN * 128);
    // K2: edges -> g_M0 / g_M1
    k_edge<<<444, 256, 18944 * 4>>>(ef, ea, idx_i, idx_j, Wr0, Wr1, Wr2, Wr3);
    // K3: message -> out[0 .. NN*128)
    k_out<<<592, 128>>>(Ws0, Ws1, out);
}

// round 2
// speedup vs baseline: 1.0031x; 1.0031x over previous
#include <cuda_runtime.h>
#include <math.h>

#define NN 50000
#define NE 600000

// Scratch (allocation-free: static __device__ globals)
__device__ float g_X [NN * 128];   // [n][m(0..3)][c]  m=0 -> x0, m=1..3 -> x1
__device__ float g_M0[NN * 64];    // [n][s(0:p0,1:p3)][c]
__device__ float g_M1[NN * 288];   // [n][p(0:p1,1:p2,2:p4)][m(0..2)][c]

__device__ __forceinline__ float act(float x) {
    // RS * silu(x)
    return 1.6765324703310907f * x * (1.0f / (1.0f + __expf(-x)));
}

// ---------------------------------------------------------------------------
// K1: per-node skip connection (sc -> out) and first linear (x -> g_X)
// warp per node, lane = output channel w/d
// ---------------------------------------------------------------------------
__global__ void __launch_bounds__(128) k_node(
    const float* __restrict__ na,     // (N, 10)
    const float* __restrict__ nf,     // (N, 32, 4)
    const float* __restrict__ Wskip,  // (2, 32, 10, 32)
    const float* __restrict__ Wfirst, // (2, 32, 32)
    float* __restrict__ out_sc)       // out + NN*128
{
    extern __shared__ float s[];
    float* sW0  = s;          // 10240 : [c][v][w]
    float* sW1  = s + 10240;  // 10240 : [c][v][w]
    float* sWfT = s + 20480;  // 2048  : [skip][c][d]
    for (int t = threadIdx.x; t < 20480; t += blockDim.x) s[t] = Wskip[t];
    for (int t = threadIdx.x; t < 2048; t += blockDim.x) {
        int skip = t >> 10; int r = t & 1023; int d = r >> 5; int c = r & 31;
        sWfT[skip * 1024 + c * 32 + d] = Wfirst[t];
    }
    __syncthreads();

    int lane  = threadIdx.x & 31;
    int warp  = threadIdx.x >> 5;
    int nwarp = (blockDim.x >> 5) * gridDim.x;
    for (int n = blockIdx.x * (blockDim.x >> 5) + warp; n < NN; n += nwarp) {
        float nav[10];
        #pragma unroll
        for (int v = 0; v < 10; v++) nav[v] = na[n * 10 + v];

        float acc0 = 0.f, a10 = 0.f, a11 = 0.f, a12 = 0.f;
        float x0 = 0.f, x1 = 0.f, x2 = 0.f, x3 = 0.f;
        const float4* nf4 = (const float4*)(nf + (size_t)n * 128);
        #pragma unroll 4
        for (int c = 0; c < 32; c++) {
            float4 f = nf4[c];
            float A = 0.f, B = 0.f;
            #pragma unroll
            for (int v = 0; v < 10; v++) {
                A += nav[v] * sW0[(c * 10 + v) * 32 + lane];
                B += nav[v] * sW1[(c * 10 + v) * 32 + lane];
            }
            acc0 += f.x * A;
            a10  += f.y * B; a11 += f.z * B; a12 += f.w * B;
            float w0 = sWfT[c * 32 + lane];
            float w1 = sWfT[1024 + c * 32 + lane];
            x0 += f.x * w0; x1 += f.y * w1; x2 += f.z * w1; x3 += f.w * w1;
        }
        const float s320 = 0.05590169943749474f;   // 1/sqrt(320)
        const float sC   = 0.17677669529663687f;   // 1/sqrt(32)
        float4 scv = make_float4(acc0 * s320, a10 * s320, a11 * s320, a12 * s320);
        *(float4*)(out_sc + (size_t)n * 128 + lane * 4) = scv;
        float* xo = g_X + (size_t)n * 128;
        xo[lane]      = x0 * sC;
        xo[32 + lane] = x1 * sC;
        xo[64 + lane] = x2 * sC;
        xo[96 + lane] = x3 * sC;
    }
}

// ---------------------------------------------------------------------------
// K2: per-edge MLP + gather + segmented accumulation
// warp cooperates on one edge; each warp owns a contiguous chunk of (sorted) edges
// ---------------------------------------------------------------------------
__global__ void __launch_bounds__(256) k_edge(
    const float* __restrict__ ef,     // (E, 8)
    const float* __restrict__ ea,     // (E, 1, 4)
    const int*   __restrict__ idx_i,  // (E,) sorted
    const int*   __restrict__ idx_j,  // (E,)
    const float* __restrict__ Wr0,    // (64, 8)
    const float* __restrict__ Wr1,    // (64, 64)
    const float* __restrict__ Wr2,    // (64, 64)
    const float* __restrict__ Wr3)    // (160, 64)
{
    extern __shared__ float s[];
    float2* sW0  = (float2*)s;             // 256  [k][j]   (.x=j, .y=j+32)
    float2* sW1  = (float2*)(s + 512);     // 2048 [k][j]
    float2* sW2  = (float2*)(s + 4608);    // 2048 [k][j]
    float4* sW3a = (float4*)(s + 8704);    // 2048 [k][c] paths 0..3
    float*  sW3b = s + 16896;              // 2048 [k][c] path 4
    // total = 18944 floats = 75776 B

    for (int t = threadIdx.x; t < 256; t += blockDim.x) {
        int k = t >> 5, j = t & 31;
        sW0[t] = make_float2(Wr0[j * 8 + k], Wr0[(j + 32) * 8 + k]);
    }
    for (int t = threadIdx.x; t < 2048; t += blockDim.x) {
        int k = t >> 5, j = t & 31;
        sW1[t] = make_float2(Wr1[j * 64 + k], Wr1[(j + 32) * 64 + k]);
        sW2[t] = make_float2(Wr2[j * 64 + k], Wr2[(j + 32) * 64 + k]);
        int c = j;
        sW3a[t] = make_float4(Wr3[c * 64 + k], Wr3[(32 + c) * 64 + k],
                              Wr3[(64 + c) * 64 + k], Wr3[(96 + c) * 64 + k]);
        sW3b[t] = Wr3[(128 + c) * 64 + k];
    }
    __syncthreads();

    int lane = threadIdx.x & 31;
    int gw   = blockIdx.x * (blockDim.x >> 5) + (threadIdx.x >> 5);
    int nw   = gridDim.x * (blockDim.x >> 5);
    int per  = (NE + nw - 1) / nw;
    int e0   = gw * per;
    int e1   = (e0 + per < NE) ? (e0 + per) : NE;
    if (e0 >= e1) return;

    float a0 = 0.f, a3 = 0.f;
    float a1x = 0.f, a1y = 0.f, a1z = 0.f;
    float a2x = 0.f, a2y = 0.f, a2z = 0.f;
    float a4x = 0.f, a4y = 0.f, a4z = 0.f;
    int cur = idx_i[e0];

    for (int e = e0; e < e1; e++) {
        int ni = idx_i[e];
        if (ni != cur) {
            atomicAdd(&g_M0[(size_t)cur * 64 + lane],      a0);
            atomicAdd(&g_M0[(size_t)cur * 64 + 32 + lane], a3);
            float* m1 = g_M1 + (size_t)cur * 288 + lane;
            atomicAdd(m1 + 0,   a1x); atomicAdd(m1 + 32,  a1y); atomicAdd(m1 + 64,  a1z);
            atomicAdd(m1 + 96,  a2x); atomicAdd(m1 + 128, a2y); atomicAdd(m1 + 160, a2z);
            atomicAdd(m1 + 192, a4x); atomicAdd(m1 + 224, a4y); atomicAdd(m1 + 256, a4z);
            a0 = a3 = a1x = a1y = a1z = a2x = a2y = a2z = a4x = a4y = a4z = 0.f;
            cur = ni;
        }

        // ----- MLP: h distributed 2 values / lane (lo=h[lane], hi=h[lane+32])
        float efr = (lane < 8) ? ef[(size_t)e * 8 + lane] : 0.f;
        float lo = 0.f, hi = 0.f;
        #pragma unroll
        for (int k = 0; k < 8; k++) {
            float b = __shfl_sync(0xffffffffu, efr, k);
            float2 W = sW0[k * 32 + lane];
            lo += b * W.x; hi += b * W.y;
        }
        lo = act(lo * 0.35355339059327373f);
        hi = act(hi * 0.35355339059327373f);

        float nlo = 0.f, nhi = 0.f;
        #pragma unroll
        for (int k = 0; k < 32; k++) {
            float b = __shfl_sync(0xffffffffu, lo, k);
            float2 W = sW1[k * 32 + lane];
            nlo += b * W.x; nhi += b * W.y;
        }
        #pragma unroll
        for (int k = 0; k < 32; k++) {
            float b = __shfl_sync(0xffffffffu, hi, k);
            float2 W = sW1[(k + 32) * 32 + lane];
            nlo += b * W.x; nhi += b * W.y;
        }
        lo = act(nlo * 0.125f); hi = act(nhi * 0.125f);

        nlo = 0.f; nhi = 0.f;
        #pragma unroll
        for (int k = 0; k < 32; k++) {
            float b = __shfl_sync(0xffffffffu, lo, k);
            float2 W = sW2[k * 32 + lane];
            nlo += b * W.x; nhi += b * W.y;
        }
        #pragma unroll
        for (int k = 0; k < 32; k++) {
            float b = __shfl_sync(0xffffffffu, hi, k);
            float2 W = sW2[(k + 32) * 32 + lane];
            nlo += b * W.x; nhi += b * W.y;
        }
        lo = act(nlo * 0.125f); hi = act(nhi * 0.125f);

        float w0 = 0.f, w1 = 0.f, w2 = 0.f, w3 = 0.f, w4 = 0.f;
        #pragma unroll
        for (int k = 0; k < 32; k++) {
            float b = __shfl_sync(0xffffffffu, lo, k);
            float4 W = sW3a[k * 32 + lane];
            float  V = sW3b[k * 32 + lane];
            w0 += b * W.x; w1 += b * W.y; w2 += b * W.z; w3 += b * W.w; w4 += b * V;
        }
        #pragma unroll
        for (int k = 0; k < 32; k++) {
            float b = __shfl_sync(0xffffffffu, hi, k);
            float4 W = sW3a[(k + 32) * 32 + lane];
            float  V = sW3b[(k + 32) * 32 + lane];
            w0 += b * W.x; w1 += b * W.y; w2 += b * W.z; w3 += b * W.w; w4 += b * V;
        }
        w0 *= 0.125f; w1 *= 0.125f; w2 *= 0.125f; w3 *= 0.125f; w4 *= 0.125f;

        // ----- gather + path products (lane = channel c)
        int j = idx_j[e];
        const float* xb = g_X + (size_t)j * 128;
        float xj0 = xb[lane];
        float xa  = xb[32 + lane];
        float xbv = xb[64 + lane];
        float xc  = xb[96 + lane];
        float4 y = *(const float4*)(ea + (size_t)e * 4);  // y0, y1x, y1y, y1z

        a0 += w0 * xj0 * y.x;
        float t1 = w1 * xj0;
        a1x += t1 * y.y; a1y += t1 * y.z; a1z += t1 * y.w;
        a2x += w2 * xa * y.x; a2y += w2 * xbv * y.x; a2z += w2 * xc * y.x;
        a3  += w3 * (xa * y.y + xbv * y.z + xc * y.w);
        a4x += w4 * (xbv * y.w - xc * y.z);
        a4y += w4 * (xc * y.y - xa * y.w);
        a4z += w4 * (xa * y.z - xbv * y.y);
    }
    // final flush
    atomicAdd(&g_M0[(size_t)cur * 64 + lane],      a0);
    atomicAdd(&g_M0[(size_t)cur * 64 + 32 + lane], a3);
    float* m1 = g_M1 + (size_t)cur * 288 + lane;
    atomicAdd(m1 + 0,   a1x); atomicAdd(m1 + 32,  a1y); atomicAdd(m1 + 64,  a1z);
    atomicAdd(m1 + 96,  a2x); atomicAdd(m1 + 128, a2y); atomicAdd(m1 + 160, a2z);
    atomicAdd(m1 + 192, a4x); atomicAdd(m1 + 224, a4y); atomicAdd(m1 + 256, a4z);
}

// ---------------------------------------------------------------------------
// K3: per-node second linear -> message output. warp per node, lane = d
// ---------------------------------------------------------------------------
__global__ void __launch_bounds__(128) k_out(
    const float* __restrict__ Ws0,  // (32, 64)
    const float* __restrict__ Ws1,  // (32, 96)
    float* __restrict__ out)        // message at out[0 .. NN*128)
{
    __shared__ float sW0T[64 * 32];   // [t=p*32+c][d]
    __shared__ float sW1T[96 * 32];   // [t=p*32+c][d]
    for (int t = threadIdx.x; t < 2048; t += blockDim.x) {
        int d = t >> 6, k = t & 63;
        sW0T[k * 32 + d] = Ws0[t];
    }
    for (int t = threadIdx.x; t < 3072; t += blockDim.x) {
        int d = t / 96, k = t % 96;
        sW1T[k * 32 + d] = Ws1[t];
    }
    __syncthreads();

    int lane  = threadIdx.x & 31;
    int warp  = threadIdx.x >> 5;
    int nwarp = (blockDim.x >> 5) * gridDim.x;
    const float sA  = 1.0f / 12.0f;
    const float s64 = 0.125f;
    const float s96 = 0.10206207261596575f;

    for (int n = blockIdx.x * (blockDim.x >> 5) + warp; n < NN; n += nwarp) {
        const float4* m0 = (const float4*)(g_M0 + (size_t)n * 64);
        float o0 = 0.f;
        #pragma unroll
        for (int t = 0; t < 16; t++) {
            float4 v = m0[t];
            o0 += v.x * sW0T[(t * 4 + 0) * 32 + lane]
                + v.y * sW0T[(t * 4 + 1) * 32 + lane]
                + v.z * sW0T[(t * 4 + 2) * 32 + lane]
                + v.w * sW0T[(t * 4 + 3) * 32 + lane];
        }
        float o1x = 0.f, o1y = 0.f, o1z = 0.f;
        #pragma unroll
        for (int p = 0; p < 3; p++) {
            const float4* m1 = (const float4*)(g_M1 + (size_t)n * 288 + p * 96);
            #pragma unroll
            for (int q = 0; q < 8; q++) {
                float4 vx = m1[q];        // m=0
                float4 vy = m1[8 + q];    // m=1
                float4 vz = m1[16 + q];   // m=2
                float wA = sW1T[(p * 32 + q * 4 + 0) * 32 + lane];
                float wB = sW1T[(p * 32 + q * 4 + 1) * 32 + lane];
                float wC = sW1T[(p * 32 + q * 4 + 2) * 32 + lane];
                float wD = sW1T[(p * 32 + q * 4 + 3) * 32 + lane];
                o1x += vx.x * wA + vx.y * wB + vx.z * wC + vx.w * wD;
                o1y += vy.x * wA + vy.y * wB + vy.z * wC + vy.w * wD;
                o1z += vz.x * wA + vz.y * wB + vz.z * wC + vz.w * wD;
            }
        }
        float4 r = make_float4(o0 * s64 * sA, o1x * s96 * sA, o1y * s96 * sA, o1z * s96 * sA);
        *(float4*)(out + (size_t)n * 128 + lane * 4) = r;
    }
}

// ---------------------------------------------------------------------------
extern "C" void kernel_launch(void* const* d_in, const int* in_sizes, int n_in,
                              void* d_out, int out_size)
{
    const float* na     = (const float*)d_in[0];   // node_attrs
    const float* nf     = (const float*)d_in[1];   // node_feats
    const float* ea     = (const float*)d_in[2];   // edge_attrs
    const float* ef     = (const float*)d_in[3];   // edge_feats
    const float* Wfirst = (const float*)d_in[4];
    const float* Wr0    = (const float*)d_in[5];
    const float* Wr1    = (const float*)d_in[6];
    const float* Wr2    = (const float*)d_in[7];
    const float* Wr3    = (const float*)d_in[8];
    const float* Ws0    = (const float*)d_in[9];
    const float* Ws1    = (const float*)d_in[10];
    const float* Wskip  = (const float*)d_in[11];
    const int*   idx_i  = (const int*)d_in[12];
    const int*   idx_j  = (const int*)d_in[13];
    float* out = (float*)d_out;

    cudaFuncSetAttribute(k_node, cudaFuncAttributeMaxDynamicSharedMemorySize, 22528 * 4);
    cudaFuncSetAttribute(k_edge, cudaFuncAttributeMaxDynamicSharedMemorySize, 18944 * 4);

    void *pM0, *pM1;
    cudaGetSymbolAddress(&pM0, g_M0);
    cudaGetSymbolAddress(&pM1, g_M1);
    cudaMemsetAsync(pM0, 0, sizeof(float) * NN * 64, 0);
    cudaMemsetAsync(pM1, 0, sizeof(float) * NN * 288, 0);

    // K1: sc -> out[NN*128 ..), x -> g_X
    k_node<<<296, 128, 22528 * 4>>>(na, nf, Wskip, Wfirst, out + (size_t)NN * 128);
    // K2: edges -> g_M0 / g_M1
    k_edge<<<444, 256, 18944 * 4>>>(ef, ea, idx_i, idx_j, Wr0, Wr1, Wr2, Wr3);
    // K3: message -> out[0 .. NN*128)
    k_out<<<592, 128>>>(Ws0, Ws1, out);
}

// round 3
// speedup vs baseline: 1.8376x; 1.8319x over previous
#include <cuda_runtime.h>
#include <math.h>

#define NN 50000
#define NE 600000

// Scratch (allocation-free: static __device__ globals)
__device__ float g_X [NN * 128];   // [n][m(0..3)][c]  m=0 -> x0, m=1..3 -> x1
__device__ float g_M0[NN * 64];    // [n][s(0:p0,1:p3)][c]
__device__ float g_M1[NN * 288];   // [n][p(0:p1,1:p2,2:p4)][m(0..2)][c]

__device__ __forceinline__ float act(float x) {
    // RS * silu(x)
    return 1.6765324703310907f * x * (1.0f / (1.0f + __expf(-x)));
}

// ---------------------------------------------------------------------------
// K1: per-node skip connection (sc -> out) and first linear (x -> g_X)
// warp per node, lane = output channel w/d. float2-packed skip weights.
// ---------------------------------------------------------------------------
__global__ void __launch_bounds__(256) k_node(
    const float* __restrict__ na,     // (N, 10)
    const float* __restrict__ nf,     // (N, 32, 4)
    const float* __restrict__ Wskip,  // (2, 32, 10, 32)
    const float* __restrict__ Wfirst, // (2, 32, 32)
    float* __restrict__ out_sc)       // out + NN*128
{
    extern __shared__ float s[];
    // [0,10240)      : skip0 packed ((c*5+vp)*32 + w)*2 + parity
    // [10240,20480)  : skip1 packed
    // [20480,22528)  : WfirstT [skip][c][d]
    for (int t = threadIdx.x; t < 10240; t += blockDim.x) {
        int c = t / 320; int v = (t / 32) % 10; int w = t & 31;
        int dst = ((c * 5 + (v >> 1)) * 32 + w) * 2 + (v & 1);
        s[dst]         = Wskip[t];
        s[10240 + dst] = Wskip[10240 + t];
    }
    for (int t = threadIdx.x; t < 2048; t += blockDim.x) {
        int skip = t >> 10; int r = t & 1023; int d = r >> 5; int c = r & 31;
        s[20480 + skip * 1024 + c * 32 + d] = Wfirst[t];
    }
    __syncthreads();
    const float2* sW0p = (const float2*)s;
    const float2* sW1p = (const float2*)(s + 10240);
    const float*  sWfT = s + 20480;

    int lane  = threadIdx.x & 31;
    int warp  = threadIdx.x >> 5;
    int nwarp = (blockDim.x >> 5) * gridDim.x;
    for (int n = blockIdx.x * (blockDim.x >> 5) + warp; n < NN; n += nwarp) {
        float2 nav2[5];
        #pragma unroll
        for (int vp = 0; vp < 5; vp++)
            nav2[vp] = make_float2(na[n * 10 + 2 * vp], na[n * 10 + 2 * vp + 1]);

        float acc0 = 0.f, a10 = 0.f, a11 = 0.f, a12 = 0.f;
        float x0 = 0.f, x1 = 0.f, x2 = 0.f, x3 = 0.f;
        const float4* nf4 = (const float4*)(nf + (size_t)n * 128);
        #pragma unroll 4
        for (int c = 0; c < 32; c++) {
            float4 f = nf4[c];
            float A = 0.f, B = 0.f;
            #pragma unroll
            for (int vp = 0; vp < 5; vp++) {
                float2 W0 = sW0p[(c * 5 + vp) * 32 + lane];
                float2 W1 = sW1p[(c * 5 + vp) * 32 + lane];
                A += nav2[vp].x * W0.x + nav2[vp].y * W0.y;
                B += nav2[vp].x * W1.x + nav2[vp].y * W1.y;
            }
            acc0 += f.x * A;
            a10  += f.y * B; a11 += f.z * B; a12 += f.w * B;
            float w0 = sWfT[c * 32 + lane];
            float w1 = sWfT[1024 + c * 32 + lane];
            x0 += f.x * w0; x1 += f.y * w1; x2 += f.z * w1; x3 += f.w * w1;
        }
        const float s320 = 0.05590169943749474f;   // 1/sqrt(320)
        const float sC   = 0.17677669529663687f;   // 1/sqrt(32)
        float4 scv = make_float4(acc0 * s320, a10 * s320, a11 * s320, a12 * s320);
        *(float4*)(out_sc + (size_t)n * 128 + lane * 4) = scv;
        float* xo = g_X + (size_t)n * 128;
        xo[lane]      = x0 * sC;
        xo[32 + lane] = x1 * sC;
        xo[64 + lane] = x2 * sC;
        xo[96 + lane] = x3 * sC;
    }
}

// ---------------------------------------------------------------------------
// K2: per-edge MLP + gather + segmented accumulation
// 4 edges per warp iteration: each weight LDS amortized over 4 edges.
// ---------------------------------------------------------------------------
__global__ void __launch_bounds__(256) k_edge(
    const float* __restrict__ ef,     // (E, 8)
    const float* __restrict__ ea,     // (E, 1, 4)
    const int*   __restrict__ idx_i,  // (E,) sorted
    const int*   __restrict__ idx_j,  // (E,)
    const float* __restrict__ Wr0,    // (64, 8)
    const float* __restrict__ Wr1,    // (64, 64)
    const float* __restrict__ Wr2,    // (64, 64)
    const float* __restrict__ Wr3)    // (160, 64)
{
    extern __shared__ float s[];
    float2* sW0  = (float2*)s;             // 256  [k][j]   (.x=j, .y=j+32)
    float2* sW1  = (float2*)(s + 512);     // 2048 [k][j]
    float2* sW2  = (float2*)(s + 4608);    // 2048 [k][j]
    float4* sW3a = (float4*)(s + 8704);    // 2048 [k][c] paths 0..3
    float*  sW3b = s + 16896;              // 2048 [k][c] path 4
    // total = 18944 floats = 75776 B

    for (int t = threadIdx.x; t < 256; t += blockDim.x) {
        int k = t >> 5, j = t & 31;
        sW0[t] = make_float2(Wr0[j * 8 + k], Wr0[(j + 32) * 8 + k]);
    }
    for (int t = threadIdx.x; t < 2048; t += blockDim.x) {
        int k = t >> 5, j = t & 31;
        sW1[t] = make_float2(Wr1[j * 64 + k], Wr1[(j + 32) * 64 + k]);
        sW2[t] = make_float2(Wr2[j * 64 + k], Wr2[(j + 32) * 64 + k]);
        int c = j;
        sW3a[t] = make_float4(Wr3[c * 64 + k], Wr3[(32 + c) * 64 + k],
                              Wr3[(64 + c) * 64 + k], Wr3[(96 + c) * 64 + k]);
        sW3b[t] = Wr3[(128 + c) * 64 + k];
    }
    __syncthreads();

    int lane = threadIdx.x & 31;
    int gw   = blockIdx.x * (blockDim.x >> 5) + (threadIdx.x >> 5);
    int nw   = gridDim.x * (blockDim.x >> 5);
    const int NG = NE / 4;                  // 150000 groups of 4 edges
    int per = (NG + nw - 1) / nw;
    int g0  = gw * per;
    int g1  = (g0 + per < NG) ? (g0 + per) : NG;
    if (g0 >= g1) return;

    float a0 = 0.f, a3 = 0.f;
    float a1x = 0.f, a1y = 0.f, a1z = 0.f;
    float a2x = 0.f, a2y = 0.f, a2z = 0.f;
    float a4x = 0.f, a4y = 0.f, a4z = 0.f;
    int cur = idx_i[g0 * 4];
    const float c8 = 0.35355339059327373f;  // 1/sqrt(8)
    const float c64 = 0.125f;               // 1/sqrt(64)

    for (int g = g0; g < g1; g++) {
        int ebase = g * 4;
        // ef for 4 edges: lane l holds ef[ebase + l/8][l%8]
        float efreg = ef[(size_t)ebase * 8 + lane];

        float lo[4], hi[4];
        #pragma unroll
        for (int r = 0; r < 4; r++) { lo[r] = 0.f; hi[r] = 0.f; }

        // ---- layer 0: 8 -> 64
        #pragma unroll
        for (int k = 0; k < 8; k++) {
            float2 W = sW0[k * 32 + lane];
            #pragma unroll
            for (int r = 0; r < 4; r++) {
                float b = __shfl_sync(0xffffffffu, efreg, r * 8 + k);
                lo[r] += b * W.x; hi[r] += b * W.y;
            }
        }
        #pragma unroll
        for (int r = 0; r < 4; r++) { lo[r] = act(lo[r] * c8); hi[r] = act(hi[r] * c8); }

        // ---- layer 1: 64 -> 64
        {
            float nlo[4] = {0.f,0.f,0.f,0.f}, nhi[4] = {0.f,0.f,0.f,0.f};
            #pragma unroll 8
            for (int k = 0; k < 32; k++) {
                float2 W = sW1[k * 32 + lane];
                #pragma unroll
                for (int r = 0; r < 4; r++) {
                    float b = __shfl_sync(0xffffffffu, lo[r], k);
                    nlo[r] += b * W.x; nhi[r] += b * W.y;
                }
            }
            #pragma unroll 8
            for (int k = 0; k < 32; k++) {
                float2 W = sW1[(k + 32) * 32 + lane];
                #pragma unroll
                for (int r = 0; r < 4; r++) {
                    float b = __shfl_sync(0xffffffffu, hi[r], k);
                    nlo[r] += b * W.x; nhi[r] += b * W.y;
                }
            }
            #pragma unroll
            for (int r = 0; r < 4; r++) { lo[r] = act(nlo[r] * c64); hi[r] = act(nhi[r] * c64); }
        }

        // ---- layer 2: 64 -> 64
        {
            float nlo[4] = {0.f,0.f,0.f,0.f}, nhi[4] = {0.f,0.f,0.f,0.f};
            #pragma unroll 8
            for (int k = 0; k < 32; k++) {
                float2 W = sW2[k * 32 + lane];
                #pragma unroll
                for (int r = 0; r < 4; r++) {
                    float b = __shfl_sync(0xffffffffu, lo[r], k);
                    nlo[r] += b * W.x; nhi[r] += b * W.y;
                }
            }
            #pragma unroll 8
            for (int k = 0; k < 32; k++) {
                float2 W = sW2[(k + 32) * 32 + lane];
                #pragma unroll
                for (int r = 0; r < 4; r++) {
                    float b = __shfl_sync(0xffffffffu, hi[r], k);
                    nlo[r] += b * W.x; nhi[r] += b * W.y;
                }
            }
            #pragma unroll
            for (int r = 0; r < 4; r++) { lo[r] = act(nlo[r] * c64); hi[r] = act(nhi[r] * c64); }
        }

        // ---- layer 3: 64 -> 160 (5 paths x 32 channels, lane = channel)
        float w0[4] = {0.f,0.f,0.f,0.f}, w1[4] = {0.f,0.f,0.f,0.f}, w2[4] = {0.f,0.f,0.f,0.f};
        float w3[4] = {0.f,0.f,0.f,0.f}, w4[4] = {0.f,0.f,0.f,0.f};
        #pragma unroll 8
        for (int k = 0; k < 32; k++) {
            float4 W = sW3a[k * 32 + lane];
            float  V = sW3b[k * 32 + lane];
            #pragma unroll
            for (int r = 0; r < 4; r++) {
                float b = __shfl_sync(0xffffffffu, lo[r], k);
                w0[r] += b * W.x; w1[r] += b * W.y; w2[r] += b * W.z;
                w3[r] += b * W.w; w4[r] += b * V;
            }
        }
        #pragma unroll 8
        for (int k = 0; k < 32; k++) {
            float4 W = sW3a[(k + 32) * 32 + lane];
            float  V = sW3b[(k + 32) * 32 + lane];
            #pragma unroll
            for (int r = 0; r < 4; r++) {
                float b = __shfl_sync(0xffffffffu, hi[r], k);
                w0[r] += b * W.x; w1[r] += b * W.y; w2[r] += b * W.z;
                w3[r] += b * W.w; w4[r] += b * V;
            }
        }

        // ---- epilogue: gather + products + segmented accumulation
        int4 ii = *(const int4*)(idx_i + ebase);
        int4 jj = *(const int4*)(idx_j + ebase);
        int iarr[4] = {ii.x, ii.y, ii.z, ii.w};
        int jarr[4] = {jj.x, jj.y, jj.z, jj.w};

        #pragma unroll
        for (int r = 0; r < 4; r++) {
            int ni = iarr[r];
            if (ni != cur) {
                atomicAdd(&g_M0[(size_t)cur * 64 + lane],      a0);
                atomicAdd(&g_M0[(size_t)cur * 64 + 32 + lane], a3);
                float* m1 = g_M1 + (size_t)cur * 288 + lane;
                atomicAdd(m1 + 0,   a1x); atomicAdd(m1 + 32,  a1y); atomicAdd(m1 + 64,  a1z);
                atomicAdd(m1 + 96,  a2x); atomicAdd(m1 + 128, a2y); atomicAdd(m1 + 160, a2z);
                atomicAdd(m1 + 192, a4x); atomicAdd(m1 + 224, a4y); atomicAdd(m1 + 256, a4z);
                a0 = a3 = a1x = a1y = a1z = a2x = a2y = a2z = a4x = a4y = a4z = 0.f;
                cur = ni;
            }
            int e = ebase + r;
            int j = jarr[r];
            const float* xb = g_X + (size_t)j * 128;
            float xj0 = xb[lane];
            float xa  = xb[32 + lane];
            float xbv = xb[64 + lane];
            float xc  = xb[96 + lane];
            float4 y = *(const float4*)(ea + (size_t)e * 4);  // y0, y1x, y1y, y1z

            float v0 = w0[r] * c64, v1 = w1[r] * c64, v2 = w2[r] * c64;
            float v3 = w3[r] * c64, v4 = w4[r] * c64;

            a0 += v0 * xj0 * y.x;
            float t1 = v1 * xj0;
            a1x += t1 * y.y; a1y += t1 * y.z; a1z += t1 * y.w;
            a2x += v2 * xa * y.x; a2y += v2 * xbv * y.x; a2z += v2 * xc * y.x;
            a3  += v3 * (xa * y.y + xbv * y.z + xc * y.w);
            a4x += v4 * (xbv * y.w - xc * y.z);
            a4y += v4 * (xc * y.y - xa * y.w);
            a4z += v4 * (xa * y.z - xbv * y.y);
        }
    }
    // final flush
    atomicAdd(&g_M0[(size_t)cur * 64 + lane],      a0);
    atomicAdd(&g_M0[(size_t)cur * 64 + 32 + lane], a3);
    float* m1 = g_M1 + (size_t)cur * 288 + lane;
    atomicAdd(m1 + 0,   a1x); atomicAdd(m1 + 32,  a1y); atomicAdd(m1 + 64,  a1z);
    atomicAdd(m1 + 96,  a2x); atomicAdd(m1 + 128, a2y); atomicAdd(m1 + 160, a2z);
    atomicAdd(m1 + 192, a4x); atomicAdd(m1 + 224, a4y); atomicAdd(m1 + 256, a4z);
}

// ---------------------------------------------------------------------------
// K3: per-node second linear -> message output. warp per node, lane = d
// ---------------------------------------------------------------------------
__global__ void __launch_bounds__(128) k_out(
    const float* __restrict__ Ws0,  // (32, 64)
    const float* __restrict__ Ws1,  // (32, 96)
    float* __restrict__ out)        // message at out[0 .. NN*128)
{
    __shared__ float sW0T[64 * 32];   // [t=p*32+c][d]
    __shared__ float sW1T[96 * 32];   // [t=p*32+c][d]
    for (int t = threadIdx.x; t < 2048; t += blockDim.x) {
        int d = t >> 6, k = t & 63;
        sW0T[k * 32 + d] = Ws0[t];
    }
    for (int t = threadIdx.x; t < 3072; t += blockDim.x) {
        int d = t / 96, k = t % 96;
        sW1T[k * 32 + d] = Ws1[t];
    }
    __syncthreads();

    int lane  = threadIdx.x & 31;
    int warp  = threadIdx.x >> 5;
    int nwarp = (blockDim.x >> 5) * gridDim.x;
    const float sA  = 1.0f / 12.0f;
    const float s64 = 0.125f;
    const float s96 = 0.10206207261596575f;

    for (int n = blockIdx.x * (blockDim.x >> 5) + warp; n < NN; n += nwarp) {
        const float4* m0 = (const float4*)(g_M0 + (size_t)n * 64);
        float o0 = 0.f;
        #pragma unroll
        for (int t = 0; t < 16; t++) {
            float4 v = m0[t];
            o0 += v.x * sW0T[(t * 4 + 0) * 32 + lane]
                + v.y * sW0T[(t * 4 + 1) * 32 + lane]
                + v.z * sW0T[(t * 4 + 2) * 32 + lane]
                + v.w * sW0T[(t * 4 + 3) * 32 + lane];
        }
        float o1x = 0.f, o1y = 0.f, o1z = 0.f;
        #pragma unroll
        for (int p = 0; p < 3; p++) {
            const float4* m1 = (const float4*)(g_M1 + (size_t)n * 288 + p * 96);
            #pragma unroll
            for (int q = 0; q < 8; q++) {
                float4 vx = m1[q];        // m=0
                float4 vy = m1[8 + q];    // m=1
                float4 vz = m1[16 + q];   // m=2
                float wA = sW1T[(p * 32 + q * 4 + 0) * 32 + lane];
                float wB = sW1T[(p * 32 + q * 4 + 1) * 32 + lane];
                float wC = sW1T[(p * 32 + q * 4 + 2) * 32 + lane];
                float wD = sW1T[(p * 32 + q * 4 + 3) * 32 + lane];
                o1x += vx.x * wA + vx.y * wB + vx.z * wC + vx.w * wD;
                o1y += vy.x * wA + vy.y * wB + vy.z * wC + vy.w * wD;
                o1z += vz.x * wA + vz.y * wB + vz.z * wC + vz.w * wD;
            }
        }
        float4 r = make_float4(o0 * s64 * sA, o1x * s96 * sA, o1y * s96 * sA, o1z * s96 * sA);
        *(float4*)(out + (size_t)n * 128 + lane * 4) = r;
    }
}

// ---------------------------------------------------------------------------
extern "C" void kernel_launch(void* const* d_in, const int* in_sizes, int n_in,
                              void* d_out, int out_size)
{
    const float* na     = (const float*)d_in[0];   // node_attrs
    const float* nf     = (const float*)d_in[1];   // node_feats
    const float* ea     = (const float*)d_in[2];   // edge_attrs
    const float* ef     = (const float*)d_in[3];   // edge_feats
    const float* Wfirst = (const float*)d_in[4];
    const float* Wr0    = (const float*)d_in[5];
    const float* Wr1    = (const float*)d_in[6];
    const float* Wr2    = (const float*)d_in[7];
    const float* Wr3    = (const float*)d_in[8];
    const float* Ws0    = (const float*)d_in[9];
    const float* Ws1    = (const float*)d_in[10];
    const float* Wskip  = (const float*)d_in[11];
    const int*   idx_i  = (const int*)d_in[12];
    const int*   idx_j  = (const int*)d_in[13];
    float* out = (float*)d_out;

    cudaFuncSetAttribute(k_node, cudaFuncAttributeMaxDynamicSharedMemorySize, 22528 * 4);
    cudaFuncSetAttribute(k_edge, cudaFuncAttributeMaxDynamicSharedMemorySize, 18944 * 4);

    void *pM0, *pM1;
    cudaGetSymbolAddress(&pM0, g_M0);
    cudaGetSymbolAddress(&pM1, g_M1);
    cudaMemsetAsync(pM0, 0, sizeof(float) * NN * 64, 0);
    cudaMemsetAsync(pM1, 0, sizeof(float) * NN * 288, 0);

    // K1: sc -> out[NN*128 ..), x -> g_X
    k_node<<<296, 256, 22528 * 4>>>(na, nf, Wskip, Wfirst, out + (size_t)NN * 128);
    // K2: edges -> g_M0 / g_M1
    k_edge<<<444, 256, 18944 * 4>>>(ef, ea, idx_i, idx_j, Wr0, Wr1, Wr2, Wr3);
    // K3: message -> out[0 .. NN*128)
    k_out<<<592, 128>>>(Ws0, Ws1, out);
}

// round 4
// speedup vs baseline: 2.2649x; 1.2326x over previous
#include <cuda_runtime.h>
#include <math.h>

#define NN 50000
#define NE 600000

typedef unsigned long long u64;

// Scratch (allocation-free: static __device__ globals)
__device__ float g_X [NN * 128];   // [n][m(0..3)][c]
__device__ float g_M0[NN * 64];    // [n][s(0:p0,1:p3)][c]
__device__ float g_M1[NN * 288];   // [n][p(0:p1,1:p2,2:p4)][m(0..2)][c]

__device__ __forceinline__ float act(float x) {
    return 1.6765324703310907f * x * (1.0f / (1.0f + __expf(-x)));
}

__device__ __forceinline__ u64 ffma2(u64 a, u64 b, u64 c) {
    u64 d;
    asm("fma.rn.f32x2 %0, %1, %2, %3;" : "=l"(d) : "l"(a), "l"(b), "l"(c));
    return d;
}
__device__ __forceinline__ u64 dup2(float x) {
    u64 d;
    asm("mov.b64 %0, {%1, %1};" : "=l"(d) : "f"(x));
    return d;
}
__device__ __forceinline__ u64 pk2(float lo, float hi) {
    u64 d;
    asm("mov.b64 %0, {%1, %2};" : "=l"(d) : "f"(lo), "f"(hi));
    return d;
}
__device__ __forceinline__ void upk2(u64 v, float& lo, float& hi) {
    asm("mov.b64 {%0, %1}, %2;" : "=f"(lo), "=f"(hi) : "l"(v));
}

// ---------------------------------------------------------------------------
// K1: per-node skip + first linear. 2 nodes per warp iteration.
// ---------------------------------------------------------------------------
__global__ void __launch_bounds__(512) k_node(
    const float* __restrict__ na,     // (N, 10)
    const float* __restrict__ nf,     // (N, 32, 4)
    const float* __restrict__ Wskip,  // (2, 32, 10, 32)
    const float* __restrict__ Wfirst, // (2, 32, 32)
    float* __restrict__ out_sc)       // out + NN*128
{
    extern __shared__ float s[];
    // [0,10240): skip0 packed ((c*5+vp)*32+w)*2+parity ; [10240,20480): skip1 ; [20480,22528): WfT
    for (int t = threadIdx.x; t < 10240; t += blockDim.x) {
        int c = t / 320; int v = (t / 32) % 10; int w = t & 31;
        int dst = ((c * 5 + (v >> 1)) * 32 + w) * 2 + (v & 1);
        s[dst]         = Wskip[t];
        s[10240 + dst] = Wskip[10240 + t];
    }
    for (int t = threadIdx.x; t < 2048; t += blockDim.x) {
        int skip = t >> 10; int r = t & 1023; int d = r >> 5; int c = r & 31;
        s[20480 + skip * 1024 + c * 32 + d] = Wfirst[t];
    }
    __syncthreads();
    const float2* sW0p = (const float2*)s;
    const float2* sW1p = (const float2*)(s + 10240);
    const float*  sWfT = s + 20480;

    int lane  = threadIdx.x & 31;
    int warp  = threadIdx.x >> 5;
    int nwarp = (blockDim.x >> 5) * gridDim.x;
    const int NT = NN / 2;   // 25000 tasks of 2 nodes

    for (int t = blockIdx.x * (blockDim.x >> 5) + warp; t < NT; t += nwarp) {
        int n0 = 2 * t, n1 = 2 * t + 1;
        float2 na0[5], na1[5];
        #pragma unroll
        for (int vp = 0; vp < 5; vp++) {
            na0[vp] = make_float2(na[n0 * 10 + 2 * vp], na[n0 * 10 + 2 * vp + 1]);
            na1[vp] = make_float2(na[n1 * 10 + 2 * vp], na[n1 * 10 + 2 * vp + 1]);
        }
        const float4* f0 = (const float4*)(nf + (size_t)n0 * 128);
        const float4* f1 = (const float4*)(nf + (size_t)n1 * 128);

        float sc0_0 = 0.f, sc1_0 = 0.f, sc2_0 = 0.f, sc3_0 = 0.f;
        float sc0_1 = 0.f, sc1_1 = 0.f, sc2_1 = 0.f, sc3_1 = 0.f;
        float x0_0 = 0.f, x1_0 = 0.f, x2_0 = 0.f, x3_0 = 0.f;
        float x0_1 = 0.f, x1_1 = 0.f, x2_1 = 0.f, x3_1 = 0.f;

        #pragma unroll 4
        for (int c = 0; c < 32; c++) {
            float4 fa = f0[c];
            float4 fb = f1[c];
            float A0 = 0.f, B0 = 0.f, A1 = 0.f, B1 = 0.f;
            #pragma unroll
            for (int vp = 0; vp < 5; vp++) {
                float2 W0 = sW0p[(c * 5 + vp) * 32 + lane];
                float2 W1 = sW1p[(c * 5 + vp) * 32 + lane];
                A0 += na0[vp].x * W0.x + na0[vp].y * W0.y;
                B0 += na0[vp].x * W1.x + na0[vp].y * W1.y;
                A1 += na1[vp].x * W0.x + na1[vp].y * W0.y;
                B1 += na1[vp].x * W1.x + na1[vp].y * W1.y;
            }
            sc0_0 += fa.x * A0; sc1_0 += fa.y * B0; sc2_0 += fa.z * B0; sc3_0 += fa.w * B0;
            sc0_1 += fb.x * A1; sc1_1 += fb.y * B1; sc2_1 += fb.z * B1; sc3_1 += fb.w * B1;
            float w0 = sWfT[c * 32 + lane];
            float w1 = sWfT[1024 + c * 32 + lane];
            x0_0 += fa.x * w0; x1_0 += fa.y * w1; x2_0 += fa.z * w1; x3_0 += fa.w * w1;
            x0_1 += fb.x * w0; x1_1 += fb.y * w1; x2_1 += fb.z * w1; x3_1 += fb.w * w1;
        }
        const float s320 = 0.05590169943749474f;
        const float sC   = 0.17677669529663687f;
        *(float4*)(out_sc + (size_t)n0 * 128 + lane * 4) =
            make_float4(sc0_0 * s320, sc1_0 * s320, sc2_0 * s320, sc3_0 * s320);
        *(float4*)(out_sc + (size_t)n1 * 128 + lane * 4) =
            make_float4(sc0_1 * s320, sc1_1 * s320, sc2_1 * s320, sc3_1 * s320);
        float* xo0 = g_X + (size_t)n0 * 128;
        xo0[lane] = x0_0 * sC; xo0[32 + lane] = x1_0 * sC;
        xo0[64 + lane] = x2_0 * sC; xo0[96 + lane] = x3_0 * sC;
        float* xo1 = g_X + (size_t)n1 * 128;
        xo1[lane] = x0_1 * sC; xo1[32 + lane] = x1_1 * sC;
        xo1[64 + lane] = x2_1 * sC; xo1[96 + lane] = x3_1 * sC;
    }
}

// ---------------------------------------------------------------------------
// 64->64 layer with f32x2 FFMA + smem staging (no shuffles)
// ---------------------------------------------------------------------------
__device__ __forceinline__ void layer64(const float2* __restrict__ sW,
                                        float2* __restrict__ stg,
                                        u64 h[4], int lane, float scale)
{
    __syncwarp();
    #pragma unroll
    for (int r = 0; r < 4; r++) *(u64*)&stg[r * 32 + lane] = h[r];
    __syncwarp();
    u64 acc[4] = {0ull, 0ull, 0ull, 0ull};
    #pragma unroll
    for (int kk = 0; kk < 16; kk++) {
        u64 wA = *(const u64*)&sW[(2 * kk)      * 32 + lane];
        u64 wB = *(const u64*)&sW[(2 * kk + 32) * 32 + lane];
        u64 wC = *(const u64*)&sW[(2 * kk + 1)  * 32 + lane];
        u64 wD = *(const u64*)&sW[(2 * kk + 33) * 32 + lane];
        #pragma unroll
        for (int r = 0; r < 4; r++) {
            float4 b = *(const float4*)&stg[r * 32 + kk * 2];
            acc[r] = ffma2(dup2(b.x), wA, acc[r]);
            acc[r] = ffma2(dup2(b.y), wB, acc[r]);
            acc[r] = ffma2(dup2(b.z), wC, acc[r]);
            acc[r] = ffma2(dup2(b.w), wD, acc[r]);
        }
    }
    #pragma unroll
    for (int r = 0; r < 4; r++) {
        float lo, hi; upk2(acc[r], lo, hi);
        h[r] = pk2(act(lo * scale), act(hi * scale));
    }
}

// ---------------------------------------------------------------------------
// K2: per-edge MLP + gather + segmented accumulation (4 edges/warp iter)
// ---------------------------------------------------------------------------
__global__ void __launch_bounds__(256, 2) k_edge(
    const float* __restrict__ ef,     // (E, 8)
    const float* __restrict__ ea,     // (E, 1, 4)
    const int*   __restrict__ idx_i,  // (E,) sorted
    const int*   __restrict__ idx_j,  // (E,)
    const float* __restrict__ Wr0,    // (64, 8)
    const float* __restrict__ Wr1,    // (64, 64)
    const float* __restrict__ Wr2,    // (64, 64)
    const float* __restrict__ Wr3)    // (160, 64)
{
    extern __shared__ float s[];
    float2* sW0  = (float2*)s;             // 256  [k][j]
    float2* sW1  = (float2*)(s + 512);     // 2048 [k][j]
    float2* sW2  = (float2*)(s + 4608);    // 2048 [k][j]
    float4* sW3a = (float4*)(s + 8704);    // 2048 [k][c]
    float*  sW3b = s + 16896;              // 2048 [k][c]
    float2* stgAll = (float2*)(s + 18944); // 8 warps x 128 float2

    for (int t = threadIdx.x; t < 256; t += blockDim.x) {
        int k = t >> 5, j = t & 31;
        sW0[t] = make_float2(Wr0[j * 8 + k], Wr0[(j + 32) * 8 + k]);
    }
    for (int t = threadIdx.x; t < 2048; t += blockDim.x) {
        int k = t >> 5, j = t & 31;
        sW1[t] = make_float2(Wr1[j * 64 + k], Wr1[(j + 32) * 64 + k]);
        sW2[t] = make_float2(Wr2[j * 64 + k], Wr2[(j + 32) * 64 + k]);
        int c = j;
        sW3a[t] = make_float4(Wr3[c * 64 + k], Wr3[(32 + c) * 64 + k],
                              Wr3[(64 + c) * 64 + k], Wr3[(96 + c) * 64 + k]);
        sW3b[t] = Wr3[(128 + c) * 64 + k];
    }
    __syncthreads();

    int lane = threadIdx.x & 31;
    float2* stg = stgAll + (threadIdx.x >> 5) * 128;

    int gw = blockIdx.x * (blockDim.x >> 5) + (threadIdx.x >> 5);
    int nw = gridDim.x * (blockDim.x >> 5);
    const int NG = NE / 4;
    int per = (NG + nw - 1) / nw;
    int g0  = gw * per;
    int g1  = (g0 + per < NG) ? (g0 + per) : NG;
    if (g0 >= g1) return;

    float a0 = 0.f, a3 = 0.f;
    float a1x = 0.f, a1y = 0.f, a1z = 0.f;
    float a2x = 0.f, a2y = 0.f, a2z = 0.f;
    float a4x = 0.f, a4y = 0.f, a4z = 0.f;
    int cur = idx_i[g0 * 4];
    const float c8  = 0.35355339059327373f;
    const float c64 = 0.125f;

    for (int g = g0; g < g1; g++) {
        int ebase = g * 4;
        float efreg = ef[(size_t)ebase * 8 + lane];

        // ---- layer 0: 8 -> 64 (shfl broadcast, only 32 per group)
        u64 h[4] = {0ull, 0ull, 0ull, 0ull};
        #pragma unroll
        for (int k = 0; k < 8; k++) {
            u64 w = *(const u64*)&sW0[k * 32 + lane];
            #pragma unroll
            for (int r = 0; r < 4; r++) {
                float b = __shfl_sync(0xffffffffu, efreg, r * 8 + k);
                h[r] = ffma2(dup2(b), w, h[r]);
            }
        }
        #pragma unroll
        for (int r = 0; r < 4; r++) {
            float lo, hi; upk2(h[r], lo, hi);
            h[r] = pk2(act(lo * c8), act(hi * c8));
        }

        // ---- layers 1, 2
        layer64(sW1, stg, h, lane, c64);
        layer64(sW2, stg, h, lane, c64);

        // ---- layer 3: 64 -> 160
        __syncwarp();
        #pragma unroll
        for (int r = 0; r < 4; r++) *(u64*)&stg[r * 32 + lane] = h[r];
        __syncwarp();
        u64 acc01[4] = {0ull, 0ull, 0ull, 0ull};
        u64 acc23[4] = {0ull, 0ull, 0ull, 0ull};
        float acc4[4] = {0.f, 0.f, 0.f, 0.f};
        #pragma unroll
        for (int kk = 0; kk < 16; kk++) {
            int ks0 = 2 * kk, ks1 = 2 * kk + 32, ks2 = 2 * kk + 1, ks3 = 2 * kk + 33;
            float4 A0 = sW3a[ks0 * 32 + lane]; float V0 = sW3b[ks0 * 32 + lane];
            float4 A1 = sW3a[ks1 * 32 + lane]; float V1 = sW3b[ks1 * 32 + lane];
            float4 A2 = sW3a[ks2 * 32 + lane]; float V2 = sW3b[ks2 * 32 + lane];
            float4 A3 = sW3a[ks3 * 32 + lane]; float V3 = sW3b[ks3 * 32 + lane];
            u64 w01_0 = pk2(A0.x, A0.y), w23_0 = pk2(A0.z, A0.w);
            u64 w01_1 = pk2(A1.x, A1.y), w23_1 = pk2(A1.z, A1.w);
            u64 w01_2 = pk2(A2.x, A2.y), w23_2 = pk2(A2.z, A2.w);
            u64 w01_3 = pk2(A3.x, A3.y), w23_3 = pk2(A3.z, A3.w);
            #pragma unroll
            for (int r = 0; r < 4; r++) {
                float4 b = *(const float4*)&stg[r * 32 + kk * 2];
                u64 bx = dup2(b.x), by = dup2(b.y), bz = dup2(b.z), bw = dup2(b.w);
                acc01[r] = ffma2(bx, w01_0, acc01[r]);
                acc23[r] = ffma2(bx, w23_0, acc23[r]);
                acc4[r] += b.x * V0;
                acc01[r] = ffma2(by, w01_1, acc01[r]);
                acc23[r] = ffma2(by, w23_1, acc23[r]);
                acc4[r] += b.y * V1;
                acc01[r] = ffma2(bz, w01_2, acc01[r]);
                acc23[r] = ffma2(bz, w23_2, acc23[r]);
                acc4[r] += b.z * V2;
                acc01[r] = ffma2(bw, w01_3, acc01[r]);
                acc23[r] = ffma2(bw, w23_3, acc23[r]);
                acc4[r] += b.w * V3;
            }
        }

        // ---- epilogue
        int4 ii = *(const int4*)(idx_i + ebase);
        int4 jj = *(const int4*)(idx_j + ebase);
        int iarr[4] = {ii.x, ii.y, ii.z, ii.w};
        int jarr[4] = {jj.x, jj.y, jj.z, jj.w};

        #pragma unroll
        for (int r = 0; r < 4; r++) {
            int ni = iarr[r];
            if (ni != cur) {
                atomicAdd(&g_M0[(size_t)cur * 64 + lane],      a0);
                atomicAdd(&g_M0[(size_t)cur * 64 + 32 + lane], a3);
                float* m1 = g_M1 + (size_t)cur * 288 + lane;
                atomicAdd(m1 + 0,   a1x); atomicAdd(m1 + 32,  a1y); atomicAdd(m1 + 64,  a1z);
                atomicAdd(m1 + 96,  a2x); atomicAdd(m1 + 128, a2y); atomicAdd(m1 + 160, a2z);
                atomicAdd(m1 + 192, a4x); atomicAdd(m1 + 224, a4y); atomicAdd(m1 + 256, a4z);
                a0 = a3 = a1x = a1y = a1z = a2x = a2y = a2z = a4x = a4y = a4z = 0.f;
                cur = ni;
            }
            int e = ebase + r;
            int j = jarr[r];
            const float* xb = g_X + (size_t)j * 128;
            float xj0 = xb[lane];
            float xa  = xb[32 + lane];
            float xbv = xb[64 + lane];
            float xc  = xb[96 + lane];
            float4 y = *(const float4*)(ea + (size_t)e * 4);

            float w0, w1, w2, w3;
            upk2(acc01[r], w0, w1);
            upk2(acc23[r], w2, w3);
            float v0 = w0 * c64, v1 = w1 * c64, v2 = w2 * c64;
            float v3 = w3 * c64, v4 = acc4[r] * c64;

            a0 += v0 * xj0 * y.x;
            float t1 = v1 * xj0;
            a1x += t1 * y.y; a1y += t1 * y.z; a1z += t1 * y.w;
            a2x += v2 * xa * y.x; a2y += v2 * xbv * y.x; a2z += v2 * xc * y.x;
            a3  += v3 * (xa * y.y + xbv * y.z + xc * y.w);
            a4x += v4 * (xbv * y.w - xc * y.z);
            a4y += v4 * (xc * y.y - xa * y.w);
            a4z += v4 * (xa * y.z - xbv * y.y);
        }
    }
    atomicAdd(&g_M0[(size_t)cur * 64 + lane],      a0);
    atomicAdd(&g_M0[(size_t)cur * 64 + 32 + lane], a3);
    float* m1 = g_M1 + (size_t)cur * 288 + lane;
    atomicAdd(m1 + 0,   a1x); atomicAdd(m1 + 32,  a1y); atomicAdd(m1 + 64,  a1z);
    atomicAdd(m1 + 96,  a2x); atomicAdd(m1 + 128, a2y); atomicAdd(m1 + 160, a2z);
    atomicAdd(m1 + 192, a4x); atomicAdd(m1 + 224, a4y); atomicAdd(m1 + 256, a4z);
}

// ---------------------------------------------------------------------------
// K3: per-node second linear -> message output
// ---------------------------------------------------------------------------
__global__ void __launch_bounds__(128) k_out(
    const float* __restrict__ Ws0,  // (32, 64)
    const float* __restrict__ Ws1,  // (32, 96)
    float* __restrict__ out)
{
    __shared__ float sW0T[64 * 32];
    __shared__ float sW1T[96 * 32];
    for (int t = threadIdx.x; t < 2048; t += blockDim.x) {
        int d = t >> 6, k = t & 63;
        sW0T[k * 32 + d] = Ws0[t];
    }
    for (int t = threadIdx.x; t < 3072; t += blockDim.x) {
        int d = t / 96, k = t % 96;
        sW1T[k * 32 + d] = Ws1[t];
    }
    __syncthreads();

    int lane  = threadIdx.x & 31;
    int warp  = threadIdx.x >> 5;
    int nwarp = (blockDim.x >> 5) * gridDim.x;
    const float sA  = 1.0f / 12.0f;
    const float s64 = 0.125f;
    const float s96 = 0.10206207261596575f;

    for (int n = blockIdx.x * (blockDim.x >> 5) + warp; n < NN; n += nwarp) {
        const float4* m0 = (const float4*)(g_M0 + (size_t)n * 64);
        float o0 = 0.f;
        #pragma unroll
        for (int t = 0; t < 16; t++) {
            float4 v = m0[t];
            o0 += v.x * sW0T[(t * 4 + 0) * 32 + lane]
                + v.y * sW0T[(t * 4 + 1) * 32 + lane]
                + v.z * sW0T[(t * 4 + 2) * 32 + lane]
                + v.w * sW0T[(t * 4 + 3) * 32 + lane];
        }
        float o1x = 0.f, o1y = 0.f, o1z = 0.f;
        #pragma unroll
        for (int p = 0; p < 3; p++) {
            const float4* m1 = (const float4*)(g_M1 + (size_t)n * 288 + p * 96);
            #pragma unroll
            for (int q = 0; q < 8; q++) {
                float4 vx = m1[q];
                float4 vy = m1[8 + q];
                float4 vz = m1[16 + q];
                float wA = sW1T[(p * 32 + q * 4 + 0) * 32 + lane];
                float wB = sW1T[(p * 32 + q * 4 + 1) * 32 + lane];
                float wC = sW1T[(p * 32 + q * 4 + 2) * 32 + lane];
                float wD = sW1T[(p * 32 + q * 4 + 3) * 32 + lane];
                o1x += vx.x * wA + vx.y * wB + vx.z * wC + vx.w * wD;
                o1y += vy.x * wA + vy.y * wB + vy.z * wC + vy.w * wD;
                o1z += vz.x * wA + vz.y * wB + vz.z * wC + vz.w * wD;
            }
        }
        float4 r = make_float4(o0 * s64 * sA, o1x * s96 * sA, o1y * s96 * sA, o1z * s96 * sA);
        *(float4*)(out + (size_t)n * 128 + lane * 4) = r;
    }
}

// ---------------------------------------------------------------------------
extern "C" void kernel_launch(void* const* d_in, const int* in_sizes, int n_in,
                              void* d_out, int out_size)
{
    const float* na     = (const float*)d_in[0];
    const float* nf     = (const float*)d_in[1];
    const float* ea     = (const float*)d_in[2];
    const float* ef     = (const float*)d_in[3];
    const float* Wfirst = (const float*)d_in[4];
    const float* Wr0    = (const float*)d_in[5];
    const float* Wr1    = (const float*)d_in[6];
    const float* Wr2    = (const float*)d_in[7];
    const float* Wr3    = (const float*)d_in[8];
    const float* Ws0    = (const float*)d_in[9];
    const float* Ws1    = (const float*)d_in[10];
    const float* Wskip  = (const float*)d_in[11];
    const int*   idx_i  = (const int*)d_in[12];
    const int*   idx_j  = (const int*)d_in[13];
    float* out = (float*)d_out;

    cudaFuncSetAttribute(k_node, cudaFuncAttributeMaxDynamicSharedMemorySize, 22528 * 4);
    cudaFuncSetAttribute(k_edge, cudaFuncAttributeMaxDynamicSharedMemorySize, 20992 * 4);

    void *pM0, *pM1;
    cudaGetSymbolAddress(&pM0, g_M0);
    cudaGetSymbolAddress(&pM1, g_M1);
    cudaMemsetAsync(pM0, 0, sizeof(float) * NN * 64, 0);
    cudaMemsetAsync(pM1, 0, sizeof(float) * NN * 288, 0);

    k_node<<<296, 512, 22528 * 4>>>(na, nf, Wskip, Wfirst, out + (size_t)NN * 128);
    k_edge<<<296, 256, 20992 * 4>>>(ef, ea, idx_i, idx_j, Wr0, Wr1, Wr2, Wr3);
    k_out<<<592, 128>>>(Ws0, Ws1, out);
}

// round 5
// speedup vs baseline: 2.2705x; 1.0025x over previous
#include <cuda_runtime.h>
#include <math.h>

#define NN 50000
#define NE 600000

typedef unsigned long long u64;

// Scratch (allocation-free: static __device__ globals)
__device__ float g_X [NN * 128];   // [n][m(0..3)][c]
__device__ float g_M0[NN * 64];    // [n][s(0:p0,1:p3)][c]
__device__ float g_M1[NN * 288];   // [n][p(0:p1,1:p2,2:p4)][m(0..2)][c]

__device__ __forceinline__ float act(float x) {
    return 1.6765324703310907f * x * (1.0f / (1.0f + __expf(-x)));
}

__device__ __forceinline__ u64 ffma2(u64 a, u64 b, u64 c) {
    u64 d;
    asm("fma.rn.f32x2 %0, %1, %2, %3;" : "=l"(d) : "l"(a), "l"(b), "l"(c));
    return d;
}
__device__ __forceinline__ void upk2(u64 v, float& lo, float& hi) {
    asm("mov.b64 {%0, %1}, %2;" : "=f"(lo), "=f"(hi) : "l"(v));
}
__device__ __forceinline__ float hadd2(u64 v) {
    float lo, hi; upk2(v, lo, hi); return lo + hi;
}

// ---------------------------------------------------------------------------
// K1: per-node skip + first linear. 2 nodes per warp iteration.
// ---------------------------------------------------------------------------
__global__ void __launch_bounds__(512) k_node(
    const float* __restrict__ na,     // (N, 10)
    const float* __restrict__ nf,     // (N, 32, 4)
    const float* __restrict__ Wskip,  // (2, 32, 10, 32)
    const float* __restrict__ Wfirst, // (2, 32, 32)
    float* __restrict__ out_sc)       // out + NN*128
{
    extern __shared__ float s[];
    for (int t = threadIdx.x; t < 10240; t += blockDim.x) {
        int c = t / 320; int v = (t / 32) % 10; int w = t & 31;
        int dst = ((c * 5 + (v >> 1)) * 32 + w) * 2 + (v & 1);
        s[dst]         = Wskip[t];
        s[10240 + dst] = Wskip[10240 + t];
    }
    for (int t = threadIdx.x; t < 2048; t += blockDim.x) {
        int skip = t >> 10; int r = t & 1023; int d = r >> 5; int c = r & 31;
        s[20480 + skip * 1024 + c * 32 + d] = Wfirst[t];
    }
    __syncthreads();
    const float2* sW0p = (const float2*)s;
    const float2* sW1p = (const float2*)(s + 10240);
    const float*  sWfT = s + 20480;

    int lane  = threadIdx.x & 31;
    int warp  = threadIdx.x >> 5;
    int nwarp = (blockDim.x >> 5) * gridDim.x;
    const int NT = NN / 2;

    for (int t = blockIdx.x * (blockDim.x >> 5) + warp; t < NT; t += nwarp) {
        int n0 = 2 * t, n1 = 2 * t + 1;
        float2 na0[5], na1[5];
        #pragma unroll
        for (int vp = 0; vp < 5; vp++) {
            na0[vp] = make_float2(na[n0 * 10 + 2 * vp], na[n0 * 10 + 2 * vp + 1]);
            na1[vp] = make_float2(na[n1 * 10 + 2 * vp], na[n1 * 10 + 2 * vp + 1]);
        }
        const float4* f0 = (const float4*)(nf + (size_t)n0 * 128);
        const float4* f1 = (const float4*)(nf + (size_t)n1 * 128);

        float sc0_0 = 0.f, sc1_0 = 0.f, sc2_0 = 0.f, sc3_0 = 0.f;
        float sc0_1 = 0.f, sc1_1 = 0.f, sc2_1 = 0.f, sc3_1 = 0.f;
        float x0_0 = 0.f, x1_0 = 0.f, x2_0 = 0.f, x3_0 = 0.f;
        float x0_1 = 0.f, x1_1 = 0.f, x2_1 = 0.f, x3_1 = 0.f;

        #pragma unroll 4
        for (int c = 0; c < 32; c++) {
            float4 fa = f0[c];
            float4 fb = f1[c];
            float A0 = 0.f, B0 = 0.f, A1 = 0.f, B1 = 0.f;
            #pragma unroll
            for (int vp = 0; vp < 5; vp++) {
                float2 W0 = sW0p[(c * 5 + vp) * 32 + lane];
                float2 W1 = sW1p[(c * 5 + vp) * 32 + lane];
                A0 += na0[vp].x * W0.x + na0[vp].y * W0.y;
                B0 += na0[vp].x * W1.x + na0[vp].y * W1.y;
                A1 += na1[vp].x * W0.x + na1[vp].y * W0.y;
                B1 += na1[vp].x * W1.x + na1[vp].y * W1.y;
            }
            sc0_0 += fa.x * A0; sc1_0 += fa.y * B0; sc2_0 += fa.z * B0; sc3_0 += fa.w * B0;
            sc0_1 += fb.x * A1; sc1_1 += fb.y * B1; sc2_1 += fb.z * B1; sc3_1 += fb.w * B1;
            float w0 = sWfT[c * 32 + lane];
            float w1 = sWfT[1024 + c * 32 + lane];
            x0_0 += fa.x * w0; x1_0 += fa.y * w1; x2_0 += fa.z * w1; x3_0 += fa.w * w1;
            x0_1 += fb.x * w0; x1_1 += fb.y * w1; x2_1 += fb.z * w1; x3_1 += fb.w * w1;
        }
        const float s320 = 0.05590169943749474f;
        const float sC   = 0.17677669529663687f;
        *(float4*)(out_sc + (size_t)n0 * 128 + lane * 4) =
            make_float4(sc0_0 * s320, sc1_0 * s320, sc2_0 * s320, sc3_0 * s320);
        *(float4*)(out_sc + (size_t)n1 * 128 + lane * 4) =
            make_float4(sc0_1 * s320, sc1_1 * s320, sc2_1 * s320, sc3_1 * s320);
        float* xo0 = g_X + (size_t)n0 * 128;
        xo0[lane] = x0_0 * sC; xo0[32 + lane] = x1_0 * sC;
        xo0[64 + lane] = x2_0 * sC; xo0[96 + lane] = x3_0 * sC;
        float* xo1 = g_X + (size_t)n1 * 128;
        xo1[lane] = x0_1 * sC; xo1[32 + lane] = x1_1 * sC;
        xo1[64 + lane] = x2_1 * sC; xo1[96 + lane] = x3_1 * sC;
    }
}

// ---------------------------------------------------------------------------
// helpers for k_edge (8 edges per warp group, k-pair f32x2 packing)
// ---------------------------------------------------------------------------
// stage h[16] (e=0..7, half=0/1; value for feature j = half*32+lane) into stg[e*64 + j]
__device__ __forceinline__ void stage_h(float* __restrict__ stg, const float h[16], int lane) {
    __syncwarp();
    #pragma unroll
    for (int e = 0; e < 8; e++) {
        stg[e * 64 + lane]      = h[e * 2 + 0];
        stg[e * 64 + 32 + lane] = h[e * 2 + 1];
    }
    __syncwarp();
}

// 64->64 layer. sW layout: [(m*2+half)*32+lane] float2 = (W[j][2m], W[j][2m+1]), j=half*32+lane
__device__ __forceinline__ void layer64p(const float* __restrict__ sW,
                                         float* __restrict__ stg,
                                         float h[16], int lane, float scale)
{
    stage_h(stg, h, lane);
    u64 acc[16];
    #pragma unroll
    for (int i = 0; i < 16; i++) acc[i] = 0ull;
    #pragma unroll 4
    for (int m2 = 0; m2 < 16; m2++) {
        // weights for pairs m=2*m2 (even) and m=2*m2+1 (odd), both halves
        u64 w00 = *(const u64*)&sW[(((2 * m2 + 0) * 2 + 0) * 32 + lane) * 2];
        u64 w01 = *(const u64*)&sW[(((2 * m2 + 0) * 2 + 1) * 32 + lane) * 2];
        u64 w10 = *(const u64*)&sW[(((2 * m2 + 1) * 2 + 0) * 32 + lane) * 2];
        u64 w11 = *(const u64*)&sW[(((2 * m2 + 1) * 2 + 1) * 32 + lane) * 2];
        #pragma unroll
        for (int e = 0; e < 8; e++) {
            ulonglong2 bb = *(const ulonglong2*)(stg + e * 64 + m2 * 4);
            acc[e * 2 + 0] = ffma2(bb.x, w00, acc[e * 2 + 0]);
            acc[e * 2 + 1] = ffma2(bb.x, w01, acc[e * 2 + 1]);
            acc[e * 2 + 0] = ffma2(bb.y, w10, acc[e * 2 + 0]);
            acc[e * 2 + 1] = ffma2(bb.y, w11, acc[e * 2 + 1]);
        }
    }
    #pragma unroll
    for (int i = 0; i < 16; i++) h[i] = act(hadd2(acc[i]) * scale);
}

// ---------------------------------------------------------------------------
// K2: per-edge MLP + gather + segmented accumulation (8 edges/warp iter)
// ---------------------------------------------------------------------------
__global__ void __launch_bounds__(256, 2) k_edge(
    const float* __restrict__ ef,     // (E, 8)
    const float* __restrict__ ea,     // (E, 1, 4)
    const int*   __restrict__ idx_i,  // (E,) sorted
    const int*   __restrict__ idx_j,  // (E,)
    const float* __restrict__ Wr0,    // (64, 8)
    const float* __restrict__ Wr1,    // (64, 64)
    const float* __restrict__ Wr2,    // (64, 64)
    const float* __restrict__ Wr3)    // (160, 64)
{
    extern __shared__ float s[];
    // floats: sW0 [0,512)  sW1 [512,4608)  sW2 [4608,8704)  sW3 [8704,18944)
    //         staging: 8 warps x 512 floats at [18944, 23040)
    float* sW0 = s;
    float* sW1 = s + 512;
    float* sW2 = s + 4608;
    float* sW3 = s + 8704;

    // sW0: [(m*2+half)*32+lane] float2 = (Wr0[j][2m], Wr0[j][2m+1]), j=half*32+lane, m=0..3
    for (int t = threadIdx.x; t < 256; t += blockDim.x) {
        int m = t >> 6; int half = (t >> 5) & 1; int lane = t & 31;
        int j = half * 32 + lane;
        ((float2*)sW0)[t] = ((const float2*)Wr0)[j * 4 + m];
    }
    // sW1/sW2: [(m*2+half)*32+lane] float2, m=0..31
    for (int t = threadIdx.x; t < 2048; t += blockDim.x) {
        int m = t >> 6; int half = (t >> 5) & 1; int lane = t & 31;
        int j = half * 32 + lane;
        ((float2*)sW1)[t] = ((const float2*)Wr1)[j * 32 + m];
        ((float2*)sW2)[t] = ((const float2*)Wr2)[j * 32 + m];
    }
    // sW3: [(m*5+p)*32+c] float2 = (Wr3[p*32+c][2m], [2m+1]), m=0..31, p=0..4
    for (int t = threadIdx.x; t < 5120; t += blockDim.x) {
        int m = t / 160; int rem = t % 160; int p = rem >> 5; int c = rem & 31;
        ((float2*)sW3)[t] = ((const float2*)Wr3)[(p * 32 + c) * 32 + m];
    }
    __syncthreads();

    int lane = threadIdx.x & 31;
    float* stg = s + 18944 + (threadIdx.x >> 5) * 512;

    int gw = blockIdx.x * (blockDim.x >> 5) + (threadIdx.x >> 5);
    int nw = gridDim.x * (blockDim.x >> 5);
    const int NG = NE / 8;                 // 75000 groups of 8
    int per = (NG + nw - 1) / nw;
    int g0  = gw * per;
    int g1  = (g0 + per < NG) ? (g0 + per) : NG;
    if (g0 >= g1) return;

    float a0 = 0.f, a3 = 0.f;
    float a1x = 0.f, a1y = 0.f, a1z = 0.f;
    float a2x = 0.f, a2y = 0.f, a2z = 0.f;
    float a4x = 0.f, a4y = 0.f, a4z = 0.f;
    int cur = idx_i[g0 * 8];
    const float c8  = 0.35355339059327373f;
    const float c64 = 0.125f;

    for (int g = g0; g < g1; g++) {
        int ebase = g * 8;

        // ---- stage ef (8 edges x 8 floats) into stg[0..64)
        float efA = ef[(size_t)ebase * 8 + lane];
        float efB = ef[(size_t)ebase * 8 + 32 + lane];
        __syncwarp();
        stg[lane]      = efA;
        stg[32 + lane] = efB;
        __syncwarp();

        // ---- L0: 8 -> 64
        float h[16];
        {
            u64 acc[16];
            #pragma unroll
            for (int i = 0; i < 16; i++) acc[i] = 0ull;
            #pragma unroll
            for (int m = 0; m < 4; m++) {
                u64 w0 = *(const u64*)&sW0[((m * 2 + 0) * 32 + lane) * 2];
                u64 w1 = *(const u64*)&sW0[((m * 2 + 1) * 32 + lane) * 2];
                #pragma unroll
                for (int e = 0; e < 8; e++) {
                    u64 bb = *(const u64*)(stg + e * 8 + m * 2);
                    acc[e * 2 + 0] = ffma2(bb, w0, acc[e * 2 + 0]);
                    acc[e * 2 + 1] = ffma2(bb, w1, acc[e * 2 + 1]);
                }
            }
            #pragma unroll
            for (int i = 0; i < 16; i++) h[i] = act(hadd2(acc[i]) * c8);
        }

        // ---- L1, L2
        layer64p(sW1, stg, h, lane, c64);
        layer64p(sW2, stg, h, lane, c64);

        // ---- L3 + epilogue, two sub-batches of 4 edges
        stage_h(stg, h, lane);
        int4 iiA = *(const int4*)(idx_i + ebase);
        int4 iiB = *(const int4*)(idx_i + ebase + 4);
        int4 jjA = *(const int4*)(idx_j + ebase);
        int4 jjB = *(const int4*)(idx_j + ebase + 4);

        #pragma unroll
        for (int sb = 0; sb < 2; sb++) {
            u64 accP[20];   // [p][r] = accP[p*4+r]
            #pragma unroll
            for (int i = 0; i < 20; i++) accP[i] = 0ull;
            #pragma unroll 4
            for (int m2 = 0; m2 < 16; m2++) {
                ulonglong2 bb[4];
                #pragma unroll
                for (int r = 0; r < 4; r++)
                    bb[r] = *(const ulonglong2*)(stg + (sb * 4 + r) * 64 + m2 * 4);
                #pragma unroll
                for (int kkl = 0; kkl < 2; kkl++) {
                    int m = 2 * m2 + kkl;
                    u64 wp[5];
                    #pragma unroll
                    for (int p = 0; p < 5; p++)
                        wp[p] = *(const u64*)&sW3[((m * 5 + p) * 32 + lane) * 2];
                    #pragma unroll
                    for (int r = 0; r < 4; r++) {
                        u64 b = kkl ? bb[r].y : bb[r].x;
                        #pragma unroll
                        for (int p = 0; p < 5; p++)
                            accP[p * 4 + r] = ffma2(b, wp[p], accP[p * 4 + r]);
                    }
                }
            }

            int iarr[4], jarr[4];
            if (sb == 0) {
                iarr[0] = iiA.x; iarr[1] = iiA.y; iarr[2] = iiA.z; iarr[3] = iiA.w;
                jarr[0] = jjA.x; jarr[1] = jjA.y; jarr[2] = jjA.z; jarr[3] = jjA.w;
            } else {
                iarr[0] = iiB.x; iarr[1] = iiB.y; iarr[2] = iiB.z; iarr[3] = iiB.w;
                jarr[0] = jjB.x; jarr[1] = jjB.y; jarr[2] = jjB.z; jarr[3] = jjB.w;
            }

            #pragma unroll
            for (int r = 0; r < 4; r++) {
                int ni = iarr[r];
                if (ni != cur) {
                    atomicAdd(&g_M0[(size_t)cur * 64 + lane],      a0);
                    atomicAdd(&g_M0[(size_t)cur * 64 + 32 + lane], a3);
                    float* m1 = g_M1 + (size_t)cur * 288 + lane;
                    atomicAdd(m1 + 0,   a1x); atomicAdd(m1 + 32,  a1y); atomicAdd(m1 + 64,  a1z);
                    atomicAdd(m1 + 96,  a2x); atomicAdd(m1 + 128, a2y); atomicAdd(m1 + 160, a2z);
                    atomicAdd(m1 + 192, a4x); atomicAdd(m1 + 224, a4y); atomicAdd(m1 + 256, a4z);
                    a0 = a3 = a1x = a1y = a1z = a2x = a2y = a2z = a4x = a4y = a4z = 0.f;
                    cur = ni;
                }
                int e = ebase + sb * 4 + r;
                int j = jarr[r];
                const float* xb = g_X + (size_t)j * 128;
                float xj0 = xb[lane];
                float xa  = xb[32 + lane];
                float xbv = xb[64 + lane];
                float xc  = xb[96 + lane];
                float4 y = *(const float4*)(ea + (size_t)e * 4);

                float v0 = hadd2(accP[0 * 4 + r]) * c64;
                float v1 = hadd2(accP[1 * 4 + r]) * c64;
                float v2 = hadd2(accP[2 * 4 + r]) * c64;
                float v3 = hadd2(accP[3 * 4 + r]) * c64;
                float v4 = hadd2(accP[4 * 4 + r]) * c64;

                a0 += v0 * xj0 * y.x;
                float t1 = v1 * xj0;
                a1x += t1 * y.y; a1y += t1 * y.z; a1z += t1 * y.w;
                a2x += v2 * xa * y.x; a2y += v2 * xbv * y.x; a2z += v2 * xc * y.x;
                a3  += v3 * (xa * y.y + xbv * y.z + xc * y.w);
                a4x += v4 * (xbv * y.w - xc * y.z);
                a4y += v4 * (xc * y.y - xa * y.w);
                a4z += v4 * (xa * y.z - xbv * y.y);
            }
        }
    }
    // final flush
    atomicAdd(&g_M0[(size_t)cur * 64 + lane],      a0);
    atomicAdd(&g_M0[(size_t)cur * 64 + 32 + lane], a3);
    float* m1 = g_M1 + (size_t)cur * 288 + lane;
    atomicAdd(m1 + 0,   a1x); atomicAdd(m1 + 32,  a1y); atomicAdd(m1 + 64,  a1z);
    atomicAdd(m1 + 96,  a2x); atomicAdd(m1 + 128, a2y); atomicAdd(m1 + 160, a2z);
    atomicAdd(m1 + 192, a4x); atomicAdd(m1 + 224, a4y); atomicAdd(m1 + 256, a4z);
}

// ---------------------------------------------------------------------------
// K3: per-node second linear -> message output
// ---------------------------------------------------------------------------
__global__ void __launch_bounds__(128) k_out(
    const float* __restrict__ Ws0,  // (32, 64)
    const float* __restrict__ Ws1,  // (32, 96)
    float* __restrict__ out)
{
    __shared__ float sW0T[64 * 32];
    __shared__ float sW1T[96 * 32];
    for (int t = threadIdx.x; t < 2048; t += blockDim.x) {
        int d = t >> 6, k = t & 63;
        sW0T[k * 32 + d] = Ws0[t];
    }
    for (int t = threadIdx.x; t < 3072; t += blockDim.x) {
        int d = t / 96, k = t % 96;
        sW1T[k * 32 + d] = Ws1[t];
    }
    __syncthreads();

    int lane  = threadIdx.x & 31;
    int warp  = threadIdx.x >> 5;
    int nwarp = (blockDim.x >> 5) * gridDim.x;
    const float sA  = 1.0f / 12.0f;
    const float s64 = 0.125f;
    const float s96 = 0.10206207261596575f;

    for (int n = blockIdx.x * (blockDim.x >> 5) + warp; n < NN; n += nwarp) {
        const float4* m0 = (const float4*)(g_M0 + (size_t)n * 64);
        float o0 = 0.f;
        #pragma unroll
        for (int t = 0; t < 16; t++) {
            float4 v = m0[t];
            o0 += v.x * sW0T[(t * 4 + 0) * 32 + lane]
                + v.y * sW0T[(t * 4 + 1) * 32 + lane]
                + v.z * sW0T[(t * 4 + 2) * 32 + lane]
                + v.w * sW0T[(t * 4 + 3) * 32 + lane];
        }
        float o1x = 0.f, o1y = 0.f, o1z = 0.f;
        #pragma unroll
        for (int p = 0; p < 3; p++) {
            const float4* m1 = (const float4*)(g_M1 + (size_t)n * 288 + p * 96);
            #pragma unroll
            for (int q = 0; q < 8; q++) {
                float4 vx = m1[q];
                float4 vy = m1[8 + q];
                float4 vz = m1[16 + q];
                float wA = sW1T[(p * 32 + q * 4 + 0) * 32 + lane];
                float wB = sW1T[(p * 32 + q * 4 + 1) * 32 + lane];
                float wC = sW1T[(p * 32 + q * 4 + 2) * 32 + lane];
                float wD = sW1T[(p * 32 + q * 4 + 3) * 32 + lane];
                o1x += vx.x * wA + vx.y * wB + vx.z * wC + vx.w * wD;
                o1y += vy.x * wA + vy.y * wB + vy.z * wC + vy.w * wD;
                o1z += vz.x * wA + vz.y * wB + vz.z * wC + vz.w * wD;
            }
        }
        float4 r = make_float4(o0 * s64 * sA, o1x * s96 * sA, o1y * s96 * sA, o1z * s96 * sA);
        *(float4*)(out + (size_t)n * 128 + lane * 4) = r;
    }
}

// ---------------------------------------------------------------------------
extern "C" void kernel_launch(void* const* d_in, const int* in_sizes, int n_in,
                              void* d_out, int out_size)
{
    const float* na     = (const float*)d_in[0];
    const float* nf     = (const float*)d_in[1];
    const float* ea     = (const float*)d_in[2];
    const float* ef     = (const float*)d_in[3];
    const float* Wfirst = (const float*)d_in[4];
    const float* Wr0    = (const float*)d_in[5];
    const float* Wr1    = (const float*)d_in[6];
    const float* Wr2    = (const float*)d_in[7];
    const float* Wr3    = (const float*)d_in[8];
    const float* Ws0    = (const float*)d_in[9];
    const float* Ws1    = (const float*)d_in[10];
    const float* Wskip  = (const float*)d_in[11];
    const int*   idx_i  = (const int*)d_in[12];
    const int*   idx_j  = (const int*)d_in[13];
    float* out = (float*)d_out;

    cudaFuncSetAttribute(k_node, cudaFuncAttributeMaxDynamicSharedMemorySize, 22528 * 4);
    cudaFuncSetAttribute(k_edge, cudaFuncAttributeMaxDynamicSharedMemorySize, 23040 * 4);

    void *pM0, *pM1;
    cudaGetSymbolAddress(&pM0, g_M0);
    cudaGetSymbolAddress(&pM1, g_M1);
    cudaMemsetAsync(pM0, 0, sizeof(float) * NN * 64, 0);
    cudaMemsetAsync(pM1, 0, sizeof(float) * NN * 288, 0);

    k_node<<<296, 512, 22528 * 4>>>(na, nf, Wskip, Wfirst, out + (size_t)NN * 128);
    k_edge<<<296, 256, 23040 * 4>>>(ef, ea, idx_i, idx_j, Wr0, Wr1, Wr2, Wr3);
    k_out<<<592, 128>>>(Ws0, Ws1, out);
}

// round 6
// speedup vs baseline: 2.6602x; 1.1716x over previous
#include <cuda_runtime.h>
#include <cuda_bf16.h>
#include <math.h>

#define NN 50000
#define NE 600000

typedef unsigned int u32;

// Scratch (allocation-free: static __device__ globals)
__device__ float g_X [NN * 128];   // [n][m(0..3)][c]
__device__ float g_M0[NN * 64];    // [n][s(0:p0,1:p3)][c]
__device__ float g_M1[NN * 288];   // [n][p(0:p1,1:p2,2:p4)][m(0..2)][c]

__device__ __forceinline__ float act(float x) {
    return 1.6765324703310907f * x * (1.0f / (1.0f + __expf(-x)));
}

// split-pack a pair (v0 -> lower half / even col, v1 -> upper half / odd col)
// returns {hi-part packed bf16x2, residual packed bf16x2}
__device__ __forceinline__ uint2 bsplit2(float v0, float v1) {
    u32 h;
    asm("cvt.rn.bf16x2.f32 %0, %1, %2;" : "=r"(h) : "f"(v1), "f"(v0)); // hi=v1, lo=v0
    float h0 = __uint_as_float(h << 16);
    float h1 = __uint_as_float(h & 0xFFFF0000u);
    float r0 = v0 - h0, r1 = v1 - h1;
    u32 l;
    asm("cvt.rn.bf16x2.f32 %0, %1, %2;" : "=r"(l) : "f"(r1), "f"(r0));
    return make_uint2(h, l);
}

__device__ __forceinline__ void mma16816(float* d, u32 a0, u32 a1, u32 a2, u32 a3,
                                         u32 b0, u32 b1) {
    asm("mma.sync.aligned.m16n8k16.row.col.f32.bf16.bf16.f32 "
        "{%0,%1,%2,%3}, {%4,%5,%6,%7}, {%8,%9}, {%0,%1,%2,%3};"
        : "+f"(d[0]), "+f"(d[1]), "+f"(d[2]), "+f"(d[3])
        : "r"(a0), "r"(a1), "r"(a2), "r"(a3), "r"(b0), "r"(b1));
}

// ---------------------------------------------------------------------------
// K1: per-node skip + first linear. 2 nodes per warp iteration. (unchanged)
// ---------------------------------------------------------------------------
__global__ void __launch_bounds__(512) k_node(
    const float* __restrict__ na,     // (N, 10)
    const float* __restrict__ nf,     // (N, 32, 4)
    const float* __restrict__ Wskip,  // (2, 32, 10, 32)
    const float* __restrict__ Wfirst, // (2, 32, 32)
    float* __restrict__ out_sc)       // out + NN*128
{
    extern __shared__ float s[];
    for (int t = threadIdx.x; t < 10240; t += blockDim.x) {
        int c = t / 320; int v = (t / 32) % 10; int w = t & 31;
        int dst = ((c * 5 + (v >> 1)) * 32 + w) * 2 + (v & 1);
        s[dst]         = Wskip[t];
        s[10240 + dst] = Wskip[10240 + t];
    }
    for (int t = threadIdx.x; t < 2048; t += blockDim.x) {
        int skip = t >> 10; int r = t & 1023; int d = r >> 5; int c = r & 31;
        s[20480 + skip * 1024 + c * 32 + d] = Wfirst[t];
    }
    __syncthreads();
    const float2* sW0p = (const float2*)s;
    const float2* sW1p = (const float2*)(s + 10240);
    const float*  sWfT = s + 20480;

    int lane  = threadIdx.x & 31;
    int warp  = threadIdx.x >> 5;
    int nwarp = (blockDim.x >> 5) * gridDim.x;
    const int NT = NN / 2;

    for (int t = blockIdx.x * (blockDim.x >> 5) + warp; t < NT; t += nwarp) {
        int n0 = 2 * t, n1 = 2 * t + 1;
        float2 na0[5], na1[5];
        #pragma unroll
        for (int vp = 0; vp < 5; vp++) {
            na0[vp] = make_float2(na[n0 * 10 + 2 * vp], na[n0 * 10 + 2 * vp + 1]);
            na1[vp] = make_float2(na[n1 * 10 + 2 * vp], na[n1 * 10 + 2 * vp + 1]);
        }
        const float4* f0 = (const float4*)(nf + (size_t)n0 * 128);
        const float4* f1 = (const float4*)(nf + (size_t)n1 * 128);

        float sc0_0 = 0.f, sc1_0 = 0.f, sc2_0 = 0.f, sc3_0 = 0.f;
        float sc0_1 = 0.f, sc1_1 = 0.f, sc2_1 = 0.f, sc3_1 = 0.f;
        float x0_0 = 0.f, x1_0 = 0.f, x2_0 = 0.f, x3_0 = 0.f;
        float x0_1 = 0.f, x1_1 = 0.f, x2_1 = 0.f, x3_1 = 0.f;

        #pragma unroll 4
        for (int c = 0; c < 32; c++) {
            float4 fa = f0[c];
            float4 fb = f1[c];
            float A0 = 0.f, B0 = 0.f, A1 = 0.f, B1 = 0.f;
            #pragma unroll
            for (int vp = 0; vp < 5; vp++) {
                float2 W0 = sW0p[(c * 5 + vp) * 32 + lane];
                float2 W1 = sW1p[(c * 5 + vp) * 32 + lane];
                A0 += na0[vp].x * W0.x + na0[vp].y * W0.y;
                B0 += na0[vp].x * W1.x + na0[vp].y * W1.y;
                A1 += na1[vp].x * W0.x + na1[vp].y * W0.y;
                B1 += na1[vp].x * W1.x + na1[vp].y * W1.y;
            }
            sc0_0 += fa.x * A0; sc1_0 += fa.y * B0; sc2_0 += fa.z * B0; sc3_0 += fa.w * B0;
            sc0_1 += fb.x * A1; sc1_1 += fb.y * B1; sc2_1 += fb.z * B1; sc3_1 += fb.w * B1;
            float w0 = sWfT[c * 32 + lane];
            float w1 = sWfT[1024 + c * 32 + lane];
            x0_0 += fa.x * w0; x1_0 += fa.y * w1; x2_0 += fa.z * w1; x3_0 += fa.w * w1;
            x0_1 += fb.x * w0; x1_1 += fb.y * w1; x2_1 += fb.z * w1; x3_1 += fb.w * w1;
        }
        const float s320 = 0.05590169943749474f;
        const float sC   = 0.17677669529663687f;
        *(float4*)(out_sc + (size_t)n0 * 128 + lane * 4) =
            make_float4(sc0_0 * s320, sc1_0 * s320, sc2_0 * s320, sc3_0 * s320);
        *(float4*)(out_sc + (size_t)n1 * 128 + lane * 4) =
            make_float4(sc0_1 * s320, sc1_1 * s320, sc2_1 * s320, sc3_1 * s320);
        float* xo0 = g_X + (size_t)n0 * 128;
        xo0[lane] = x0_0 * sC; xo0[32 + lane] = x1_0 * sC;
        xo0[64 + lane] = x2_0 * sC; xo0[96 + lane] = x3_0 * sC;
        float* xo1 = g_X + (size_t)n1 * 128;
        xo1[lane] = x0_1 * sC; xo1[32 + lane] = x1_1 * sC;
        xo1[64 + lane] = x2_1 * sC; xo1[96 + lane] = x3_1 * sC;
    }
}

// ---------------------------------------------------------------------------
// act + split-pack D[8][4] back into bf16 h/l staging
// ---------------------------------------------------------------------------
__device__ __forceinline__ void act_store(float D[8][4], float scale,
                                          u32* stgH, u32* stgL, int g, int tq)
{
    __syncwarp();
    #pragma unroll
    for (int nt = 0; nt < 8; nt++) {
        float v0 = act(D[nt][0] * scale), v1 = act(D[nt][1] * scale);
        float v2 = act(D[nt][2] * scale), v3 = act(D[nt][3] * scale);
        uint2 p01 = bsplit2(v0, v1);
        uint2 p23 = bsplit2(v2, v3);
        stgH[g * 33 + nt * 4 + tq]       = p01.x;
        stgL[g * 33 + nt * 4 + tq]       = p01.y;
        stgH[(g + 8) * 33 + nt * 4 + tq] = p23.x;
        stgL[(g + 8) * 33 + nt * 4 + tq] = p23.y;
    }
    __syncwarp();
}

// 64->64 layer via mma (3-term bf16 split)
__device__ __forceinline__ void layer_mma(const uint4* __restrict__ sB,
                                          u32* stgH, u32* stgL,
                                          int lane, int g, int tq, float scale)
{
    float D[8][4];
    #pragma unroll
    for (int nt = 0; nt < 8; nt++)
        D[nt][0] = D[nt][1] = D[nt][2] = D[nt][3] = 0.f;
    #pragma unroll
    for (int kt = 0; kt < 4; kt++) {
        u32 Ah0 = stgH[g * 33 + kt * 8 + tq];
        u32 Ah1 = stgH[(g + 8) * 33 + kt * 8 + tq];
        u32 Ah2 = stgH[g * 33 + kt * 8 + tq + 4];
        u32 Ah3 = stgH[(g + 8) * 33 + kt * 8 + tq + 4];
        u32 Al0 = stgL[g * 33 + kt * 8 + tq];
        u32 Al1 = stgL[(g + 8) * 33 + kt * 8 + tq];
        u32 Al2 = stgL[g * 33 + kt * 8 + tq + 4];
        u32 Al3 = stgL[(g + 8) * 33 + kt * 8 + tq + 4];
        #pragma unroll
        for (int nt = 0; nt < 8; nt++) {
            uint4 B = sB[(kt * 8 + nt) * 32 + lane];
            mma16816(D[nt], Ah0, Ah1, Ah2, Ah3, B.x, B.y);
            mma16816(D[nt], Al0, Al1, Al2, Al3, B.x, B.y);
            mma16816(D[nt], Ah0, Ah1, Ah2, Ah3, B.z, B.w);
        }
    }
    act_store(D, scale, stgH, stgL, g, tq);
}

// ---------------------------------------------------------------------------
// K2: edge MLP on tensor cores (16 edges/warp tile) + scalar epilogue
// ---------------------------------------------------------------------------
__global__ void __launch_bounds__(256, 1) k_edge(
    const float* __restrict__ ef,     // (E, 8)
    const float* __restrict__ ea,     // (E, 1, 4)
    const int*   __restrict__ idx_i,  // (E,) sorted
    const int*   __restrict__ idx_j,  // (E,)
    const float* __restrict__ Wr0,    // (64, 8)
    const float* __restrict__ Wr1,    // (64, 64)
    const float* __restrict__ Wr2,    // (64, 64)
    const float* __restrict__ Wr3)    // (160, 64)
{
    extern __shared__ float s[];
    // float offsets: sB0 [0,1024) sB1 [1024,5120) sB2 [5120,9216) sB3 [9216,19456)
    // per-warp staging: 2624 floats at 19456 + wid*2624 (8 warps -> end 40448)
    uint4* sB0 = (uint4*)s;
    uint4* sB1 = (uint4*)(s + 1024);
    uint4* sB2 = (uint4*)(s + 5120);
    uint4* sB3 = (uint4*)(s + 9216);

    int tid  = threadIdx.x;
    int lane = tid & 31;
    int g    = lane >> 2;     // mma group row
    int tq   = lane & 3;      // mma thread-in-group

    // ---- prepack weights into fragment-ready {bh0,bh1,bl0,bl1} uint4s
    for (int t = tid; t < 256; t += 256) {
        int nt = t >> 5;
        int j = nt * 8 + g, kb = 2 * tq;
        uint2 P0 = bsplit2(Wr0[j * 8 + kb], Wr0[j * 8 + kb + 1]);
        sB0[t] = make_uint4(P0.x, 0u, P0.y, 0u);     // K rows 8..15 are zero
    }
    for (int t = tid; t < 1024; t += 256) {
        int kt = t >> 8, nt = (t >> 5) & 7;
        int j = nt * 8 + g, kb = kt * 16 + 2 * tq;
        {
            uint2 P0 = bsplit2(Wr1[j * 64 + kb],     Wr1[j * 64 + kb + 1]);
            uint2 P1 = bsplit2(Wr1[j * 64 + kb + 8], Wr1[j * 64 + kb + 9]);
            sB1[t] = make_uint4(P0.x, P1.x, P0.y, P1.y);
        }
        {
            uint2 P0 = bsplit2(Wr2[j * 64 + kb],     Wr2[j * 64 + kb + 1]);
            uint2 P1 = bsplit2(Wr2[j * 64 + kb + 8], Wr2[j * 64 + kb + 9]);
            sB2[t] = make_uint4(P0.x, P1.x, P0.y, P1.y);
        }
    }
    for (int t = tid; t < 2560; t += 256) {
        int kt = t / 640, rem = t % 640;
        int nt = rem >> 5;
        int j = nt * 8 + g, kb = kt * 16 + 2 * tq;
        uint2 P0 = bsplit2(Wr3[j * 64 + kb],     Wr3[j * 64 + kb + 1]);
        uint2 P1 = bsplit2(Wr3[j * 64 + kb + 8], Wr3[j * 64 + kb + 9]);
        sB3[t] = make_uint4(P0.x, P1.x, P0.y, P1.y);
    }
    __syncthreads();

    int wid = tid >> 5;
    float* wbase = s + 19456 + wid * 2624;
    u32* stgH = (u32*)wbase;          // [16][33] b32 (bf16x2 hi parts)
    u32* stgL = stgH + 528;           // [16][33] b32 (bf16x2 residuals)
    float* stgW = wbase;              // [16][164] f32, aliases stgH/stgL in L3 phase

    int gw = blockIdx.x * 8 + wid;
    int nw = gridDim.x * 8;
    const int NTILE = NE / 16;        // 37500
    int per = (NTILE + nw - 1) / nw;
    int t0 = gw * per;
    int t1 = (t0 + per < NTILE) ? (t0 + per) : NTILE;
    if (t0 >= t1) return;

    float a0 = 0.f, a3 = 0.f;
    float a1x = 0.f, a1y = 0.f, a1z = 0.f;
    float a2x = 0.f, a2y = 0.f, a2z = 0.f;
    float a4x = 0.f, a4y = 0.f, a4z = 0.f;
    int cur = idx_i[t0 * 16];
    const float c8  = 0.35355339059327373f;
    const float c64 = 0.125f;

    for (int tile = t0; tile < t1; tile++) {
        int ebase = tile * 16;

        // ---- stage ef (16 edges x 8) as split bf16x2 pairs
        float4 v = ((const float4*)(ef + (size_t)ebase * 8))[lane];
        int se = lane >> 1, cp = (lane & 1) * 2;
        uint2 pA = bsplit2(v.x, v.y);
        uint2 pB = bsplit2(v.z, v.w);
        __syncwarp();                 // epilogue of prev tile done reading stgW
        stgH[se * 33 + cp]     = pA.x; stgL[se * 33 + cp]     = pA.y;
        stgH[se * 33 + cp + 1] = pB.x; stgL[se * 33 + cp + 1] = pB.y;
        __syncwarp();

        // ---- L0: 8 -> 64 (K=8, upper half zero)
        {
            float D[8][4];
            #pragma unroll
            for (int nt = 0; nt < 8; nt++)
                D[nt][0] = D[nt][1] = D[nt][2] = D[nt][3] = 0.f;
            u32 Ah0 = stgH[g * 33 + tq];
            u32 Ah1 = stgH[(g + 8) * 33 + tq];
            u32 Al0 = stgL[g * 33 + tq];
            u32 Al1 = stgL[(g + 8) * 33 + tq];
            #pragma unroll
            for (int nt = 0; nt < 8; nt++) {
                uint4 B = sB0[nt * 32 + lane];
                mma16816(D[nt], Ah0, Ah1, 0u, 0u, B.x, B.y);
                mma16816(D[nt], Al0, Al1, 0u, 0u, B.x, B.y);
                mma16816(D[nt], Ah0, Ah1, 0u, 0u, B.z, B.w);
            }
            act_store(D, c8, stgH, stgL, g, tq);
        }

        // ---- L1, L2: 64 -> 64
        layer_mma(sB1, stgH, stgL, lane, g, tq, c64);
        layer_mma(sB2, stgH, stgL, lane, g, tq, c64);

        // ---- L3: 64 -> 160, preload A frags then two 80-col halves
        u32 Ah[4][4], Al[4][4];
        #pragma unroll
        for (int kt = 0; kt < 4; kt++) {
            Ah[kt][0] = stgH[g * 33 + kt * 8 + tq];
            Ah[kt][1] = stgH[(g + 8) * 33 + kt * 8 + tq];
            Ah[kt][2] = stgH[g * 33 + kt * 8 + tq + 4];
            Ah[kt][3] = stgH[(g + 8) * 33 + kt * 8 + tq + 4];
            Al[kt][0] = stgL[g * 33 + kt * 8 + tq];
            Al[kt][1] = stgL[(g + 8) * 33 + kt * 8 + tq];
            Al[kt][2] = stgL[g * 33 + kt * 8 + tq + 4];
            Al[kt][3] = stgL[(g + 8) * 33 + kt * 8 + tq + 4];
        }
        __syncwarp();                 // all A reads done before stgW overwrite

        #pragma unroll
        for (int half = 0; half < 2; half++) {
            float D3[10][4];
            #pragma unroll
            for (int nt = 0; nt < 10; nt++)
                D3[nt][0] = D3[nt][1] = D3[nt][2] = D3[nt][3] = 0.f;
            #pragma unroll
            for (int kt = 0; kt < 4; kt++) {
                #pragma unroll
                for (int nt = 0; nt < 10; nt++) {
                    uint4 B = sB3[(kt * 20 + half * 10 + nt) * 32 + lane];
                    mma16816(D3[nt], Ah[kt][0], Ah[kt][1], Ah[kt][2], Ah[kt][3], B.x, B.y);
                    mma16816(D3[nt], Al[kt][0], Al[kt][1], Al[kt][2], Al[kt][3], B.x, B.y);
                    mma16816(D3[nt], Ah[kt][0], Ah[kt][1], Ah[kt][2], Ah[kt][3], B.z, B.w);
                }
            }
            #pragma unroll
            for (int nt = 0; nt < 10; nt++) {
                int col = (half * 10 + nt) * 8 + 2 * tq;
                *(float2*)&stgW[g * 164 + col] =
                    make_float2(D3[nt][0] * c64, D3[nt][1] * c64);
                *(float2*)&stgW[(g + 8) * 164 + col] =
                    make_float2(D3[nt][2] * c64, D3[nt][3] * c64);
            }
        }
        __syncwarp();

        // ---- epilogue: 4 sub-batches of 4 edges (verified scalar path)
        #pragma unroll
        for (int sb = 0; sb < 4; sb++) {
            int4 ii = *(const int4*)(idx_i + ebase + sb * 4);
            int4 jj = *(const int4*)(idx_j + ebase + sb * 4);
            int iarr[4] = {ii.x, ii.y, ii.z, ii.w};
            int jarr[4] = {jj.x, jj.y, jj.z, jj.w};

            #pragma unroll
            for (int r = 0; r < 4; r++) {
                int ni = iarr[r];
                if (ni != cur) {
                    atomicAdd(&g_M0[(size_t)cur * 64 + lane],      a0);
                    atomicAdd(&g_M0[(size_t)cur * 64 + 32 + lane], a3);
                    float* m1 = g_M1 + (size_t)cur * 288 + lane;
                    atomicAdd(m1 + 0,   a1x); atomicAdd(m1 + 32,  a1y); atomicAdd(m1 + 64,  a1z);
                    atomicAdd(m1 + 96,  a2x); atomicAdd(m1 + 128, a2y); atomicAdd(m1 + 160, a2z);
                    atomicAdd(m1 + 192, a4x); atomicAdd(m1 + 224, a4y); atomicAdd(m1 + 256, a4z);
                    a0 = a3 = a1x = a1y = a1z = a2x = a2y = a2z = a4x = a4y = a4z = 0.f;
                    cur = ni;
                }
                int e = sb * 4 + r;
                int eg = ebase + e;
                int j = jarr[r];
                const float* xb = g_X + (size_t)j * 128;
                float xj0 = xb[lane];
                float xa  = xb[32 + lane];
                float xbv = xb[64 + lane];
                float xc  = xb[96 + lane];
                float4 y = *(const float4*)(ea + (size_t)eg * 4);

                const float* W = stgW + e * 164;
                float v0 = W[lane];
                float v1 = W[32 + lane];
                float v2 = W[64 + lane];
                float v3 = W[96 + lane];
                float v4 = W[128 + lane];

                a0 += v0 * xj0 * y.x;
                float t1 = v1 * xj0;
                a1x += t1 * y.y; a1y += t1 * y.z; a1z += t1 * y.w;
                a2x += v2 * xa * y.x; a2y += v2 * xbv * y.x; a2z += v2 * xc * y.x;
                a3  += v3 * (xa * y.y + xbv * y.z + xc * y.w);
                a4x += v4 * (xbv * y.w - xc * y.z);
                a4y += v4 * (xc * y.y - xa * y.w);
                a4z += v4 * (xa * y.z - xbv * y.y);
            }
        }
    }
    // final flush
    atomicAdd(&g_M0[(size_t)cur * 64 + lane],      a0);
    atomicAdd(&g_M0[(size_t)cur * 64 + 32 + lane], a3);
    float* m1 = g_M1 + (size_t)cur * 288 + lane;
    atomicAdd(m1 + 0,   a1x); atomicAdd(m1 + 32,  a1y); atomicAdd(m1 + 64,  a1z);
    atomicAdd(m1 + 96,  a2x); atomicAdd(m1 + 128, a2y); atomicAdd(m1 + 160, a2z);
    atomicAdd(m1 + 192, a4x); atomicAdd(m1 + 224, a4y); atomicAdd(m1 + 256, a4z);
}

// ---------------------------------------------------------------------------
// K3: per-node second linear -> message output (unchanged)
// ---------------------------------------------------------------------------
__global__ void __launch_bounds__(128) k_out(
    const float* __restrict__ Ws0,  // (32, 64)
    const float* __restrict__ Ws1,  // (32, 96)
    float* __restrict__ out)
{
    __shared__ float sW0T[64 * 32];
    __shared__ float sW1T[96 * 32];
    for (int t = threadIdx.x; t < 2048; t += blockDim.x) {
        int d = t >> 6, k = t & 63;
        sW0T[k * 32 + d] = Ws0[t];
    }
    for (int t = threadIdx.x; t < 3072; t += blockDim.x) {
        int d = t / 96, k = t % 96;
        sW1T[k * 32 + d] = Ws1[t];
    }
    __syncthreads();

    int lane  = threadIdx.x & 31;
    int warp  = threadIdx.x >> 5;
    int nwarp = (blockDim.x >> 5) * gridDim.x;
    const float sA  = 1.0f / 12.0f;
    const float s64 = 0.125f;
    const float s96 = 0.10206207261596575f;

    for (int n = blockIdx.x * (blockDim.x >> 5) + warp; n < NN; n += nwarp) {
        const float4* m0 = (const float4*)(g_M0 + (size_t)n * 64);
        float o0 = 0.f;
        #pragma unroll
        for (int t = 0; t < 16; t++) {
            float4 v = m0[t];
            o0 += v.x * sW0T[(t * 4 + 0) * 32 + lane]
                + v.y * sW0T[(t * 4 + 1) * 32 + lane]
                + v.z * sW0T[(t * 4 + 2) * 32 + lane]
                + v.w * sW0T[(t * 4 + 3) * 32 + lane];
        }
        float o1x = 0.f, o1y = 0.f, o1z = 0.f;
        #pragma unroll
        for (int p = 0; p < 3; p++) {
            const float4* m1 = (const float4*)(g_M1 + (size_t)n * 288 + p * 96);
            #pragma unroll
            for (int q = 0; q < 8; q++) {
                float4 vx = m1[q];
                float4 vy = m1[8 + q];
                float4 vz = m1[16 + q];
                float wA = sW1T[(p * 32 + q * 4 + 0) * 32 + lane];
                float wB = sW1T[(p * 32 + q * 4 + 1) * 32 + lane];
                float wC = sW1T[(p * 32 + q * 4 + 2) * 32 + lane];
                float wD = sW1T[(p * 32 + q * 4 + 3) * 32 + lane];
                o1x += vx.x * wA + vx.y * wB + vx.z * wC + vx.w * wD;
                o1y += vy.x * wA + vy.y * wB + vy.z * wC + vy.w * wD;
                o1z += vz.x * wA + vz.y * wB + vz.z * wC + vz.w * wD;
            }
        }
        float4 r = make_float4(o0 * s64 * sA, o1x * s96 * sA, o1y * s96 * sA, o1z * s96 * sA);
        *(float4*)(out + (size_t)n * 128 + lane * 4) = r;
    }
}

// ---------------------------------------------------------------------------
extern "C" void kernel_launch(void* const* d_in, const int* in_sizes, int n_in,
                              void* d_out, int out_size)
{
    const float* na     = (const float*)d_in[0];
    const float* nf     = (const float*)d_in[1];
    const float* ea     = (const float*)d_in[2];
    const float* ef     = (const float*)d_in[3];
    const float* Wfirst = (const float*)d_in[4];
    const float* Wr0    = (const float*)d_in[5];
    const float* Wr1    = (const float*)d_in[6];
    const float* Wr2    = (const float*)d_in[7];
    const float* Wr3    = (const float*)d_in[8];
    const float* Ws0    = (const float*)d_in[9];
    const float* Ws1    = (const float*)d_in[10];
    const float* Wskip  = (const float*)d_in[11];
    const int*   idx_i  = (const int*)d_in[12];
    const int*   idx_j  = (const int*)d_in[13];
    float* out = (float*)d_out;

    cudaFuncSetAttribute(k_node, cudaFuncAttributeMaxDynamicSharedMemorySize, 22528 * 4);
    cudaFuncSetAttribute(k_edge, cudaFuncAttributeMaxDynamicSharedMemorySize, 40448 * 4);

    void *pM0, *pM1;
    cudaGetSymbolAddress(&pM0, g_M0);
    cudaGetSymbolAddress(&pM1, g_M1);
    cudaMemsetAsync(pM0, 0, sizeof(float) * NN * 64, 0);
    cudaMemsetAsync(pM1, 0, sizeof(float) * NN * 288, 0);

    k_node<<<296, 512, 22528 * 4>>>(na, nf, Wskip, Wfirst, out + (size_t)NN * 128);
    k_edge<<<592, 256, 40448 * 4>>>(ef, ea, idx_i, idx_j, Wr0, Wr1, Wr2, Wr3);
    k_out<<<592, 128>>>(Ws0, Ws1, out);
}

// round 7
// speedup vs baseline: 3.1338x; 1.1781x over previous
#include <cuda_runtime.h>
#include <cuda_bf16.h>
#include <math.h>

#define NN 50000
#define NE 600000

typedef unsigned int u32;

// Scratch (allocation-free: static __device__ globals)
__device__ float g_X [NN * 128];   // [n][m(0..3)][c]
__device__ float g_M0[NN * 64];    // [n][s(0:p0,1:p3)][c]
__device__ float g_M1[NN * 288];   // [n][p(0:p1,1:p2,2:p4)][m(0..2)][c]

__device__ __forceinline__ float act(float x) {
    return 1.6765324703310907f * x * (1.0f / (1.0f + __expf(-x)));
}

// split-pack a pair (v0 -> low half, v1 -> high half): {hi bf16x2, residual bf16x2}
__device__ __forceinline__ uint2 bsplit2(float v0, float v1) {
    u32 h;
    asm("cvt.rn.bf16x2.f32 %0, %1, %2;" : "=r"(h) : "f"(v1), "f"(v0));
    float h0 = __uint_as_float(h << 16);
    float h1 = __uint_as_float(h & 0xFFFF0000u);
    float r0 = v0 - h0, r1 = v1 - h1;
    u32 l;
    asm("cvt.rn.bf16x2.f32 %0, %1, %2;" : "=r"(l) : "f"(r1), "f"(r0));
    return make_uint2(h, l);
}

__device__ __forceinline__ void mma16816(float* d, u32 a0, u32 a1, u32 a2, u32 a3,
                                         u32 b0, u32 b1) {
    asm("mma.sync.aligned.m16n8k16.row.col.f32.bf16.bf16.f32 "
        "{%0,%1,%2,%3}, {%4,%5,%6,%7}, {%8,%9}, {%0,%1,%2,%3};"
        : "+f"(d[0]), "+f"(d[1]), "+f"(d[2]), "+f"(d[3])
        : "r"(a0), "r"(a1), "r"(a2), "r"(a3), "r"(b0), "r"(b1));
}

#define STR 36   // staging row stride (u32): bank = (4g+tq)%32, conflict-free

// ---------------------------------------------------------------------------
// K1: per-node skip + first linear. 2 nodes per warp iteration. (unchanged)
// ---------------------------------------------------------------------------
__global__ void __launch_bounds__(512) k_node(
    const float* __restrict__ na,     // (N, 10)
    const float* __restrict__ nf,     // (N, 32, 4)
    const float* __restrict__ Wskip,  // (2, 32, 10, 32)
    const float* __restrict__ Wfirst, // (2, 32, 32)
    float* __restrict__ out_sc)       // out + NN*128
{
    extern __shared__ float s[];
    for (int t = threadIdx.x; t < 10240; t += blockDim.x) {
        int c = t / 320; int v = (t / 32) % 10; int w = t & 31;
        int dst = ((c * 5 + (v >> 1)) * 32 + w) * 2 + (v & 1);
        s[dst]         = Wskip[t];
        s[10240 + dst] = Wskip[10240 + t];
    }
    for (int t = threadIdx.x; t < 2048; t += blockDim.x) {
        int skip = t >> 10; int r = t & 1023; int d = r >> 5; int c = r & 31;
        s[20480 + skip * 1024 + c * 32 + d] = Wfirst[t];
    }
    __syncthreads();
    const float2* sW0p = (const float2*)s;
    const float2* sW1p = (const float2*)(s + 10240);
    const float*  sWfT = s + 20480;

    int lane  = threadIdx.x & 31;
    int warp  = threadIdx.x >> 5;
    int nwarp = (blockDim.x >> 5) * gridDim.x;
    const int NT = NN / 2;

    for (int t = blockIdx.x * (blockDim.x >> 5) + warp; t < NT; t += nwarp) {
        int n0 = 2 * t, n1 = 2 * t + 1;
        float2 na0[5], na1[5];
        #pragma unroll
        for (int vp = 0; vp < 5; vp++) {
            na0[vp] = make_float2(na[n0 * 10 + 2 * vp], na[n0 * 10 + 2 * vp + 1]);
            na1[vp] = make_float2(na[n1 * 10 + 2 * vp], na[n1 * 10 + 2 * vp + 1]);
        }
        const float4* f0 = (const float4*)(nf + (size_t)n0 * 128);
        const float4* f1 = (const float4*)(nf + (size_t)n1 * 128);

        float sc0_0 = 0.f, sc1_0 = 0.f, sc2_0 = 0.f, sc3_0 = 0.f;
        float sc0_1 = 0.f, sc1_1 = 0.f, sc2_1 = 0.f, sc3_1 = 0.f;
        float x0_0 = 0.f, x1_0 = 0.f, x2_0 = 0.f, x3_0 = 0.f;
        float x0_1 = 0.f, x1_1 = 0.f, x2_1 = 0.f, x3_1 = 0.f;

        #pragma unroll 4
        for (int c = 0; c < 32; c++) {
            float4 fa = f0[c];
            float4 fb = f1[c];
            float A0 = 0.f, B0 = 0.f, A1 = 0.f, B1 = 0.f;
            #pragma unroll
            for (int vp = 0; vp < 5; vp++) {
                float2 W0 = sW0p[(c * 5 + vp) * 32 + lane];
                float2 W1 = sW1p[(c * 5 + vp) * 32 + lane];
                A0 += na0[vp].x * W0.x + na0[vp].y * W0.y;
                B0 += na0[vp].x * W1.x + na0[vp].y * W1.y;
                A1 += na1[vp].x * W0.x + na1[vp].y * W0.y;
                B1 += na1[vp].x * W1.x + na1[vp].y * W1.y;
            }
            sc0_0 += fa.x * A0; sc1_0 += fa.y * B0; sc2_0 += fa.z * B0; sc3_0 += fa.w * B0;
            sc0_1 += fb.x * A1; sc1_1 += fb.y * B1; sc2_1 += fb.z * B1; sc3_1 += fb.w * B1;
            float w0 = sWfT[c * 32 + lane];
            float w1 = sWfT[1024 + c * 32 + lane];
            x0_0 += fa.x * w0; x1_0 += fa.y * w1; x2_0 += fa.z * w1; x3_0 += fa.w * w1;
            x0_1 += fb.x * w0; x1_1 += fb.y * w1; x2_1 += fb.z * w1; x3_1 += fb.w * w1;
        }
        const float s320 = 0.05590169943749474f;
        const float sC   = 0.17677669529663687f;
        *(float4*)(out_sc + (size_t)n0 * 128 + lane * 4) =
            make_float4(sc0_0 * s320, sc1_0 * s320, sc2_0 * s320, sc3_0 * s320);
        *(float4*)(out_sc + (size_t)n1 * 128 + lane * 4) =
            make_float4(sc0_1 * s320, sc1_1 * s320, sc2_1 * s320, sc3_1 * s320);
        float* xo0 = g_X + (size_t)n0 * 128;
        xo0[lane] = x0_0 * sC; xo0[32 + lane] = x1_0 * sC;
        xo0[64 + lane] = x2_0 * sC; xo0[96 + lane] = x3_0 * sC;
        float* xo1 = g_X + (size_t)n1 * 128;
        xo1[lane] = x0_1 * sC; xo1[32 + lane] = x1_1 * sC;
        xo1[64 + lane] = x2_1 * sC; xo1[96 + lane] = x3_1 * sC;
    }
}

// ---------------------------------------------------------------------------
// act + split-pack D[8][4] back into bf16 h/l staging
// ---------------------------------------------------------------------------
__device__ __forceinline__ void act_store(float D[8][4], float scale,
                                          u32* stgH, u32* stgL, int g, int tq)
{
    __syncwarp();
    #pragma unroll
    for (int nt = 0; nt < 8; nt++) {
        float v0 = act(D[nt][0] * scale), v1 = act(D[nt][1] * scale);
        float v2 = act(D[nt][2] * scale), v3 = act(D[nt][3] * scale);
        uint2 p01 = bsplit2(v0, v1);
        uint2 p23 = bsplit2(v2, v3);
        stgH[g * STR + nt * 4 + tq]       = p01.x;
        stgL[g * STR + nt * 4 + tq]       = p01.y;
        stgH[(g + 8) * STR + nt * 4 + tq] = p23.x;
        stgL[(g + 8) * STR + nt * 4 + tq] = p23.y;
    }
    __syncwarp();
}

// 64->64 layer via mma (3-term bf16 split)
__device__ __forceinline__ void layer_mma(const uint4* __restrict__ sB,
                                          u32* stgH, u32* stgL,
                                          int lane, int g, int tq, float scale)
{
    float D[8][4];
    #pragma unroll
    for (int nt = 0; nt < 8; nt++)
        D[nt][0] = D[nt][1] = D[nt][2] = D[nt][3] = 0.f;
    #pragma unroll
    for (int kt = 0; kt < 4; kt++) {
        u32 Ah0 = stgH[g * STR + kt * 8 + tq];
        u32 Ah1 = stgH[(g + 8) * STR + kt * 8 + tq];
        u32 Ah2 = stgH[g * STR + kt * 8 + tq + 4];
        u32 Ah3 = stgH[(g + 8) * STR + kt * 8 + tq + 4];
        u32 Al0 = stgL[g * STR + kt * 8 + tq];
        u32 Al1 = stgL[(g + 8) * STR + kt * 8 + tq];
        u32 Al2 = stgL[g * STR + kt * 8 + tq + 4];
        u32 Al3 = stgL[(g + 8) * STR + kt * 8 + tq + 4];
        #pragma unroll
        for (int nt = 0; nt < 8; nt++) {
            uint4 B = sB[(kt * 8 + nt) * 32 + lane];
            mma16816(D[nt], Ah0, Ah1, Ah2, Ah3, B.x, B.y);
            mma16816(D[nt], Al0, Al1, Al2, Al3, B.x, B.y);
            mma16816(D[nt], Ah0, Ah1, Ah2, Ah3, B.z, B.w);
        }
    }
    act_store(D, scale, stgH, stgL, g, tq);
}

// ---------------------------------------------------------------------------
// K2: edge MLP on tensor cores (16 edges/warp tile) + scalar epilogue
// 12 warps/CTA, grid=148 (one wave), conflict-free staging
// ---------------------------------------------------------------------------
#define KE_WARPS 12
#define KE_THREADS (KE_WARPS * 32)
// per-warp staging: 2624 floats. smem = 19456 + 12*2624 = 50944 floats = 203776 B
#define KE_SMEM_FLOATS (19456 + KE_WARPS * 2624)

__global__ void __launch_bounds__(KE_THREADS, 1) k_edge(
    const float* __restrict__ ef,     // (E, 8)
    const float* __restrict__ ea,     // (E, 1, 4)
    const int*   __restrict__ idx_i,  // (E,) sorted
    const int*   __restrict__ idx_j,  // (E,)
    const float* __restrict__ Wr0,    // (64, 8)
    const float* __restrict__ Wr1,    // (64, 64)
    const float* __restrict__ Wr2,    // (64, 64)
    const float* __restrict__ Wr3)    // (160, 64)
{
    extern __shared__ float s[];
    uint4* sB0 = (uint4*)s;            // [0,1024) floats
    uint4* sB1 = (uint4*)(s + 1024);   // [1024,5120)
    uint4* sB2 = (uint4*)(s + 5120);   // [5120,9216)
    uint4* sB3 = (uint4*)(s + 9216);   // [9216,19456)

    int tid  = threadIdx.x;
    int lane = tid & 31;
    int g    = lane >> 2;     // mma group row
    int tq   = lane & 3;      // mma thread-in-group

    // ---- prepack weights into fragment-ready {bh0,bh1,bl0,bl1} uint4s
    for (int t = tid; t < 256; t += KE_THREADS) {
        int nt = t >> 5;
        int gg = (t >> 2) & 7, tt = t & 3;
        int j = nt * 8 + gg, kb = 2 * tt;
        uint2 P0 = bsplit2(Wr0[j * 8 + kb], Wr0[j * 8 + kb + 1]);
        sB0[t] = make_uint4(P0.x, 0u, P0.y, 0u);     // K rows 8..15 are zero
    }
    for (int t = tid; t < 1024; t += KE_THREADS) {
        int kt = t >> 8, nt = (t >> 5) & 7;
        int gg = (t >> 2) & 7, tt = t & 3;
        int j = nt * 8 + gg, kb = kt * 16 + 2 * tt;
        {
            uint2 P0 = bsplit2(Wr1[j * 64 + kb],     Wr1[j * 64 + kb + 1]);
            uint2 P1 = bsplit2(Wr1[j * 64 + kb + 8], Wr1[j * 64 + kb + 9]);
            sB1[t] = make_uint4(P0.x, P1.x, P0.y, P1.y);
        }
        {
            uint2 P0 = bsplit2(Wr2[j * 64 + kb],     Wr2[j * 64 + kb + 1]);
            uint2 P1 = bsplit2(Wr2[j * 64 + kb + 8], Wr2[j * 64 + kb + 9]);
            sB2[t] = make_uint4(P0.x, P1.x, P0.y, P1.y);
        }
    }
    for (int t = tid; t < 2560; t += KE_THREADS) {
        int kt = t / 640, rem = t % 640;
        int nt = rem >> 5;
        int gg = (t >> 2) & 7, tt = t & 3;
        int j = nt * 8 + gg, kb = kt * 16 + 2 * tt;
        uint2 P0 = bsplit2(Wr3[j * 64 + kb],     Wr3[j * 64 + kb + 1]);
        uint2 P1 = bsplit2(Wr3[j * 64 + kb + 8], Wr3[j * 64 + kb + 9]);
        sB3[t] = make_uint4(P0.x, P1.x, P0.y, P1.y);
    }
    __syncthreads();

    int wid = tid >> 5;
    float* wbase = s + 19456 + wid * 2624;
    u32* stgH = (u32*)wbase;          // [16][STR] b32 (bf16x2 hi parts)
    u32* stgL = stgH + 16 * STR;      // [16][STR] b32 (bf16x2 residuals)
    float* stgW = wbase;              // [16][164] f32, aliases stgH/stgL in L3 phase

    int gw = blockIdx.x * KE_WARPS + wid;
    int nw = gridDim.x * KE_WARPS;
    const int NTILE = NE / 16;        // 37500
    int per = (NTILE + nw - 1) / nw;
    int t0 = gw * per;
    int t1 = (t0 + per < NTILE) ? (t0 + per) : NTILE;
    if (t0 >= t1) return;

    float a0 = 0.f, a3 = 0.f;
    float a1x = 0.f, a1y = 0.f, a1z = 0.f;
    float a2x = 0.f, a2y = 0.f, a2z = 0.f;
    float a4x = 0.f, a4y = 0.f, a4z = 0.f;
    int cur = idx_i[t0 * 16];
    const float c8  = 0.35355339059327373f;
    const float c64 = 0.125f;

    for (int tile = t0; tile < t1; tile++) {
        int ebase = tile * 16;

        // ---- stage ef (16 edges x 8) as split bf16x2 pairs
        float4 v = ((const float4*)(ef + (size_t)ebase * 8))[lane];
        int se = lane >> 1, cp = (lane & 1) * 2;
        uint2 pA = bsplit2(v.x, v.y);
        uint2 pB = bsplit2(v.z, v.w);
        __syncwarp();                 // epilogue of prev tile done reading stgW
        stgH[se * STR + cp]     = pA.x; stgL[se * STR + cp]     = pA.y;
        stgH[se * STR + cp + 1] = pB.x; stgL[se * STR + cp + 1] = pB.y;
        __syncwarp();

        // ---- L0: 8 -> 64 (K=8, upper half zero)
        {
            float D[8][4];
            #pragma unroll
            for (int nt = 0; nt < 8; nt++)
                D[nt][0] = D[nt][1] = D[nt][2] = D[nt][3] = 0.f;
            u32 Ah0 = stgH[g * STR + tq];
            u32 Ah1 = stgH[(g + 8) * STR + tq];
            u32 Al0 = stgL[g * STR + tq];
            u32 Al1 = stgL[(g + 8) * STR + tq];
            #pragma unroll
            for (int nt = 0; nt < 8; nt++) {
                uint4 B = sB0[nt * 32 + lane];
                mma16816(D[nt], Ah0, Ah1, 0u, 0u, B.x, B.y);
                mma16816(D[nt], Al0, Al1, 0u, 0u, B.x, B.y);
                mma16816(D[nt], Ah0, Ah1, 0u, 0u, B.z, B.w);
            }
            act_store(D, c8, stgH, stgL, g, tq);
        }

        // ---- L1, L2: 64 -> 64
        layer_mma(sB1, stgH, stgL, lane, g, tq, c64);
        layer_mma(sB2, stgH, stgL, lane, g, tq, c64);

        // ---- L3: 64 -> 160, preload A frags then two 80-col halves
        u32 Ah[4][4], Al[4][4];
        #pragma unroll
        for (int kt = 0; kt < 4; kt++) {
            Ah[kt][0] = stgH[g * STR + kt * 8 + tq];
            Ah[kt][1] = stgH[(g + 8) * STR + kt * 8 + tq];
            Ah[kt][2] = stgH[g * STR + kt * 8 + tq + 4];
            Ah[kt][3] = stgH[(g + 8) * STR + kt * 8 + tq + 4];
            Al[kt][0] = stgL[g * STR + kt * 8 + tq];
            Al[kt][1] = stgL[(g + 8) * STR + kt * 8 + tq];
            Al[kt][2] = stgL[g * STR + kt * 8 + tq + 4];
            Al[kt][3] = stgL[(g + 8) * STR + kt * 8 + tq + 4];
        }
        __syncwarp();                 // all A reads done before stgW overwrite

        #pragma unroll
        for (int half = 0; half < 2; half++) {
            float D3[10][4];
            #pragma unroll
            for (int nt = 0; nt < 10; nt++)
                D3[nt][0] = D3[nt][1] = D3[nt][2] = D3[nt][3] = 0.f;
            #pragma unroll
            for (int kt = 0; kt < 4; kt++) {
                #pragma unroll
                for (int nt = 0; nt < 10; nt++) {
                    uint4 B = sB3[(kt * 20 + half * 10 + nt) * 32 + lane];
                    mma16816(D3[nt], Ah[kt][0], Ah[kt][1], Ah[kt][2], Ah[kt][3], B.x, B.y);
                    mma16816(D3[nt], Al[kt][0], Al[kt][1], Al[kt][2], Al[kt][3], B.x, B.y);
                    mma16816(D3[nt], Ah[kt][0], Ah[kt][1], Ah[kt][2], Ah[kt][3], B.z, B.w);
                }
            }
            #pragma unroll
            for (int nt = 0; nt < 10; nt++) {
                int col = (half * 10 + nt) * 8 + 2 * tq;
                *(float2*)&stgW[g * 164 + col] =
                    make_float2(D3[nt][0] * c64, D3[nt][1] * c64);
                *(float2*)&stgW[(g + 8) * 164 + col] =
                    make_float2(D3[nt][2] * c64, D3[nt][3] * c64);
            }
        }
        __syncwarp();

        // ---- epilogue: 4 sub-batches of 4 edges
        #pragma unroll
        for (int sb = 0; sb < 4; sb++) {
            int4 ii = *(const int4*)(idx_i + ebase + sb * 4);
            int4 jj = *(const int4*)(idx_j + ebase + sb * 4);
            int iarr[4] = {ii.x, ii.y, ii.z, ii.w};
            int jarr[4] = {jj.x, jj.y, jj.z, jj.w};

            #pragma unroll
            for (int r = 0; r < 4; r++) {
                int ni = iarr[r];
                if (ni != cur) {
                    atomicAdd(&g_M0[(size_t)cur * 64 + lane],      a0);
                    atomicAdd(&g_M0[(size_t)cur * 64 + 32 + lane], a3);
                    float* m1 = g_M1 + (size_t)cur * 288 + lane;
                    atomicAdd(m1 + 0,   a1x); atomicAdd(m1 + 32,  a1y); atomicAdd(m1 + 64,  a1z);
                    atomicAdd(m1 + 96,  a2x); atomicAdd(m1 + 128, a2y); atomicAdd(m1 + 160, a2z);
                    atomicAdd(m1 + 192, a4x); atomicAdd(m1 + 224, a4y); atomicAdd(m1 + 256, a4z);
                    a0 = a3 = a1x = a1y = a1z = a2x = a2y = a2z = a4x = a4y = a4z = 0.f;
                    cur = ni;
                }
                int e = sb * 4 + r;
                int eg = ebase + e;
                int j = jarr[r];
                const float* xb = g_X + (size_t)j * 128;
                float xj0 = xb[lane];
                float xa  = xb[32 + lane];
                float xbv = xb[64 + lane];
                float xc  = xb[96 + lane];
                float4 y = *(const float4*)(ea + (size_t)eg * 4);

                const float* W = stgW + e * 164;
                float v0 = W[lane];
                float v1 = W[32 + lane];
                float v2 = W[64 + lane];
                float v3 = W[96 + lane];
                float v4 = W[128 + lane];

                a0 += v0 * xj0 * y.x;
                float t1 = v1 * xj0;
                a1x += t1 * y.y; a1y += t1 * y.z; a1z += t1 * y.w;
                a2x += v2 * xa * y.x; a2y += v2 * xbv * y.x; a2z += v2 * xc * y.x;
                a3  += v3 * (xa * y.y + xbv * y.z + xc * y.w);
                a4x += v4 * (xbv * y.w - xc * y.z);
                a4y += v4 * (xc * y.y - xa * y.w);
                a4z += v4 * (xa * y.z - xbv * y.y);
            }
        }
    }
    // final flush
    atomicAdd(&g_M0[(size_t)cur * 64 + lane],      a0);
    atomicAdd(&g_M0[(size_t)cur * 64 + 32 + lane], a3);
    float* m1 = g_M1 + (size_t)cur * 288 + lane;
    atomicAdd(m1 + 0,   a1x); atomicAdd(m1 + 32,  a1y); atomicAdd(m1 + 64,  a1z);
    atomicAdd(m1 + 96,  a2x); atomicAdd(m1 + 128, a2y); atomicAdd(m1 + 160, a2z);
    atomicAdd(m1 + 192, a4x); atomicAdd(m1 + 224, a4y); atomicAdd(m1 + 256, a4z);
}

// ---------------------------------------------------------------------------
// K3: per-node second linear -> message output (unchanged)
// ---------------------------------------------------------------------------
__global__ void __launch_bounds__(128) k_out(
    const float* __restrict__ Ws0,  // (32, 64)
    const float* __restrict__ Ws1,  // (32, 96)
    float* __restrict__ out)
{
    __shared__ float sW0T[64 * 32];
    __shared__ float sW1T[96 * 32];
    for (int t = threadIdx.x; t < 2048; t += blockDim.x) {
        int d = t >> 6, k = t & 63;
        sW0T[k * 32 + d] = Ws0[t];
    }
    for (int t = threadIdx.x; t < 3072; t += blockDim.x) {
        int d = t / 96, k = t % 96;
        sW1T[k * 32 + d] = Ws1[t];
    }
    __syncthreads();

    int lane  = threadIdx.x & 31;
    int warp  = threadIdx.x >> 5;
    int nwarp = (blockDim.x >> 5) * gridDim.x;
    const float sA  = 1.0f / 12.0f;
    const float s64 = 0.125f;
    const float s96 = 0.10206207261596575f;

    for (int n = blockIdx.x * (blockDim.x >> 5) + warp; n < NN; n += nwarp) {
        const float4* m0 = (const float4*)(g_M0 + (size_t)n * 64);
        float o0 = 0.f;
        #pragma unroll
        for (int t = 0; t < 16; t++) {
            float4 v = m0[t];
            o0 += v.x * sW0T[(t * 4 + 0) * 32 + lane]
                + v.y * sW0T[(t * 4 + 1) * 32 + lane]
                + v.z * sW0T[(t * 4 + 2) * 32 + lane]
                + v.w * sW0T[(t * 4 + 3) * 32 + lane];
        }
        float o1x = 0.f, o1y = 0.f, o1z = 0.f;
        #pragma unroll
        for (int p = 0; p < 3; p++) {
            const float4* m1 = (const float4*)(g_M1 + (size_t)n * 288 + p * 96);
            #pragma unroll
            for (int q = 0; q < 8; q++) {
                float4 vx = m1[q];
                float4 vy = m1[8 + q];
                float4 vz = m1[16 + q];
                float wA = sW1T[(p * 32 + q * 4 + 0) * 32 + lane];
                float wB = sW1T[(p * 32 + q * 4 + 1) * 32 + lane];
                float wC = sW1T[(p * 32 + q * 4 + 2) * 32 + lane];
                float wD = sW1T[(p * 32 + q * 4 + 3) * 32 + lane];
                o1x += vx.x * wA + vx.y * wB + vx.z * wC + vx.w * wD;
                o1y += vy.x * wA + vy.y * wB + vy.z * wC + vy.w * wD;
                o1z += vz.x * wA + vz.y * wB + vz.z * wC + vz.w * wD;
            }
        }
        float4 r = make_float4(o0 * s64 * sA, o1x * s96 * sA, o1y * s96 * sA, o1z * s96 * sA);
        *(float4*)(out + (size_t)n * 128 + lane * 4) = r;
    }
}

// ---------------------------------------------------------------------------
extern "C" void kernel_launch(void* const* d_in, const int* in_sizes, int n_in,
                              void* d_out, int out_size)
{
    const float* na     = (const float*)d_in[0];
    const float* nf     = (const float*)d_in[1];
    const float* ea     = (const float*)d_in[2];
    const float* ef     = (const float*)d_in[3];
    const float* Wfirst = (const float*)d_in[4];
    const float* Wr0    = (const float*)d_in[5];
    const float* Wr1    = (const float*)d_in[6];
    const float* Wr2    = (const float*)d_in[7];
    const float* Wr3    = (const float*)d_in[8];
    const float* Ws0    = (const float*)d_in[9];
    const float* Ws1    = (const float*)d_in[10];
    const float* Wskip  = (const float*)d_in[11];
    const int*   idx_i  = (const int*)d_in[12];
    const int*   idx_j  = (const int*)d_in[13];
    float* out = (float*)d_out;

    cudaFuncSetAttribute(k_node, cudaFuncAttributeMaxDynamicSharedMemorySize, 22528 * 4);
    cudaFuncSetAttribute(k_edge, cudaFuncAttributeMaxDynamicSharedMemorySize, KE_SMEM_FLOATS * 4);

    void *pM0, *pM1;
    cudaGetSymbolAddress(&pM0, g_M0);
    cudaGetSymbolAddress(&pM1, g_M1);
    cudaMemsetAsync(pM0, 0, sizeof(float) * NN * 64, 0);
    cudaMemsetAsync(pM1, 0, sizeof(float) * NN * 288, 0);

    k_node<<<296, 512, 22528 * 4>>>(na, nf, Wskip, Wfirst, out + (size_t)NN * 128);
    k_edge<<<148, KE_THREADS, KE_SMEM_FLOATS * 4>>>(ef, ea, idx_i, idx_j, Wr0, Wr1, Wr2, Wr3);
    k_out<<<592, 128>>>(Ws0, Ws1, out);
}